// round 3
// baseline (speedup 1.0000x reference)
#include <cuda_runtime.h>
#include <cuda_bf16.h>
#include <math.h>

// ---------------- problem constants ----------------
#define BB   2
#define TT   1024
#define HID  2048
#define NKH  8
#define NVH  16
#define DK   64
#define DV   128
#define KSZ  4
#define KD   (NKH*DK)          // 512
#define VD   (NVH*DV)          // 2048
#define CD   (2*KD + VD)       // 3072
#define IPD  (CD + VD + 2*NVH) // 5152
#define BT   (BB*TT)           // 2048
#define EPSR 1e-6f
#define SCALE 0.125f           // DK^-0.5

// ---------------- scratch (__device__ globals; no allocs allowed) ----------------
__device__ float g_proj [(size_t)BT * IPD];   // 42.2 MB
__device__ float g_q    [(size_t)BT * KD];    // 4 MB  (B,T,NKH,DK)
__device__ float g_k    [(size_t)BT * KD];
__device__ float g_v    [(size_t)BT * VD];    // 16 MB (B,T,NVH,DV)
__device__ float g_beta [(size_t)BT * NVH];
__device__ float g_gdec [(size_t)BT * NVH];
__device__ float g_o    [(size_t)BT * VD];    // recurrence output
__device__ float g_gate [(size_t)BT * VD];    // gated, pre-out_proj

// ---------------- f32x2 packed helpers (sm_100a) ----------------
__device__ __forceinline__ unsigned long long pack2(float lo, float hi) {
    unsigned long long r;
    asm("mov.b64 %0, {%1, %2};" : "=l"(r) : "f"(lo), "f"(hi));
    return r;
}
__device__ __forceinline__ void ffma2(unsigned long long &d, unsigned long long a, unsigned long long b) {
    asm("fma.rn.f32x2 %0, %1, %2, %0;" : "+l"(d) : "l"(a), "l"(b));
}
__device__ __forceinline__ void fmul2(unsigned long long &d, unsigned long long a, unsigned long long b) {
    asm("mul.rn.f32x2 %0, %1, %2;" : "=l"(d) : "l"(a), "l"(b));
}
__device__ __forceinline__ void fadd2(unsigned long long &d, unsigned long long a, unsigned long long b) {
    asm("add.rn.f32x2 %0, %1, %2;" : "=l"(d) : "l"(a), "l"(b));
}
__device__ __forceinline__ float lo2(unsigned long long v) { return __uint_as_float((unsigned)(v & 0xffffffffull)); }
__device__ __forceinline__ float hi2(unsigned long long v) { return __uint_as_float((unsigned)(v >> 32)); }

__device__ __forceinline__ float silu_f(float x) { return x / (1.f + expf(-x)); }

// ================= GEMM: C[M,N] = A[M,K] * B[N,K]^T  (both K-contiguous) ========
#define GTM 128
#define GTN 128
#define GTK 16

__global__ __launch_bounds__(256)
void sgemm_nt_kernel(const float* __restrict__ A, const float* __restrict__ Bw,
                     float* __restrict__ C, int M, int N, int K)
{
    __shared__ __align__(16) float As[GTK][GTM + 4];
    __shared__ __align__(16) float Bs[GTK][GTN + 4];

    const int tid = threadIdx.x;
    const int bm = blockIdx.y * GTM;
    const int bn = blockIdx.x * GTN;
    const int tx = tid & 15, ty = tid >> 4;
    const int m0 = ty * 8, n0 = tx * 8;

    unsigned long long c2[4][8];
#pragma unroll
    for (int i = 0; i < 4; i++)
#pragma unroll
        for (int j = 0; j < 8; j++) c2[i][j] = 0ull;

    const int r0 = tid >> 2;           // 0..63
    const int r1 = r0 + 64;            // 64..127
    const int kq = (tid & 3) * 4;      // 0,4,8,12

    for (int kt = 0; kt < K; kt += GTK) {
        // ---- load A tile (M rows always valid: M multiple of 128 here) ----
        {
            float4 v0 = *(const float4*)(A + (size_t)(bm + r0) * K + kt + kq);
            float4 v1 = *(const float4*)(A + (size_t)(bm + r1) * K + kt + kq);
            As[kq+0][r0]=v0.x; As[kq+1][r0]=v0.y; As[kq+2][r0]=v0.z; As[kq+3][r0]=v0.w;
            As[kq+0][r1]=v1.x; As[kq+1][r1]=v1.y; As[kq+2][r1]=v1.z; As[kq+3][r1]=v1.w;
        }
        // ---- load B tile (guard ragged N) ----
        {
            int nA = bn + r0, nB = bn + r1;
            float4 v0 = make_float4(0.f,0.f,0.f,0.f), v1 = v0;
            if (nA < N) v0 = *(const float4*)(Bw + (size_t)nA * K + kt + kq);
            if (nB < N) v1 = *(const float4*)(Bw + (size_t)nB * K + kt + kq);
            Bs[kq+0][r0]=v0.x; Bs[kq+1][r0]=v0.y; Bs[kq+2][r0]=v0.z; Bs[kq+3][r0]=v0.w;
            Bs[kq+0][r1]=v1.x; Bs[kq+1][r1]=v1.y; Bs[kq+2][r1]=v1.z; Bs[kq+3][r1]=v1.w;
        }
        __syncthreads();
#pragma unroll
        for (int kk = 0; kk < GTK; kk++) {
            unsigned long long a2[4];
            const unsigned long long* ap = (const unsigned long long*)&As[kk][m0];
            a2[0]=ap[0]; a2[1]=ap[1]; a2[2]=ap[2]; a2[3]=ap[3];
            float4 blo = *(const float4*)&Bs[kk][n0];
            float4 bhi = *(const float4*)&Bs[kk][n0 + 4];
            unsigned long long b2[8];
            b2[0]=pack2(blo.x,blo.x); b2[1]=pack2(blo.y,blo.y);
            b2[2]=pack2(blo.z,blo.z); b2[3]=pack2(blo.w,blo.w);
            b2[4]=pack2(bhi.x,bhi.x); b2[5]=pack2(bhi.y,bhi.y);
            b2[6]=pack2(bhi.z,bhi.z); b2[7]=pack2(bhi.w,bhi.w);
#pragma unroll
            for (int i = 0; i < 4; i++)
#pragma unroll
                for (int j = 0; j < 8; j++)
                    ffma2(c2[i][j], a2[i], b2[j]);
        }
        __syncthreads();
    }

    // ---- epilogue ----
#pragma unroll
    for (int i = 0; i < 4; i++) {
        int mA = bm + m0 + 2 * i;
        int n  = bn + n0;
        float lo[8], hi[8];
#pragma unroll
        for (int j = 0; j < 8; j++) { lo[j] = lo2(c2[i][j]); hi[j] = hi2(c2[i][j]); }
        if (n + 7 < N) {
            *(float4*)(C + (size_t)mA * N + n)         = make_float4(lo[0],lo[1],lo[2],lo[3]);
            *(float4*)(C + (size_t)mA * N + n + 4)     = make_float4(lo[4],lo[5],lo[6],lo[7]);
            *(float4*)(C + (size_t)(mA+1) * N + n)     = make_float4(hi[0],hi[1],hi[2],hi[3]);
            *(float4*)(C + (size_t)(mA+1) * N + n + 4) = make_float4(hi[4],hi[5],hi[6],hi[7]);
        } else {
#pragma unroll
            for (int j = 0; j < 8; j++) {
                if (n + j < N) {
                    C[(size_t)mA * N + n + j]     = lo[j];
                    C[(size_t)(mA+1) * N + n + j] = hi[j];
                }
            }
        }
    }
}

// ============ conv(q,k) + silu + l2norm, and beta/g scalars ============
// block = one (b,t), 512 threads = 16 warps; warps 0..7 -> q heads, 8..15 -> k heads
__global__ __launch_bounds__(512)
void conv_qk_kernel(const float* __restrict__ proj, const float* __restrict__ conv_w,
                    const float* __restrict__ A_log, const float* __restrict__ dt_bias,
                    float* __restrict__ qo, float* __restrict__ ko,
                    float* __restrict__ beta_o, float* __restrict__ g_o)
{
    const int bt = blockIdx.x;
    const int t  = bt & (TT - 1);
    const int warp = threadIdx.x >> 5, lane = threadIdx.x & 31;

    float r[2];
#pragma unroll
    for (int s = 0; s < 2; s++) {
        int ch = warp * 64 + s * 32 + lane;   // 0..1023 (q then k channels)
        float acc = 0.f;
#pragma unroll
        for (int kk = 0; kk < KSZ; kk++) {
            int tt = t - 3 + kk;
            float xv = (tt >= 0) ? proj[(size_t)(bt - 3 + kk) * IPD + ch] : 0.f;
            acc = fmaf(xv, conv_w[ch * KSZ + kk], acc);
        }
        r[s] = silu_f(acc);
    }
    float ss = r[0]*r[0] + r[1]*r[1];
#pragma unroll
    for (int o = 16; o; o >>= 1) ss += __shfl_xor_sync(0xffffffffu, ss, o);
    float inv = 1.f / fmaxf(sqrtf(ss), 1e-12f);

    if (warp < 8) {
        float* dst = qo + ((size_t)bt * NKH + warp) * DK;
        dst[lane] = r[0] * inv; dst[lane + 32] = r[1] * inv;
    } else {
        float* dst = ko + ((size_t)bt * NKH + (warp - 8)) * DK;
        dst[lane] = r[0] * inv; dst[lane + 32] = r[1] * inv;
    }

    if (threadIdx.x < NVH) {
        int h = threadIdx.x;
        float braw = proj[(size_t)bt * IPD + CD + VD + h];
        float araw = proj[(size_t)bt * IPD + CD + VD + NVH + h];
        beta_o[bt * NVH + h] = 1.f / (1.f + expf(-braw));
        float si = araw + dt_bias[h];
        float sp = (si > 20.f) ? si : log1pf(expf(si));
        g_o[bt * NVH + h] = -expf(A_log[h]) * sp;
    }
}

// ============ conv(v) + silu ============
__global__ __launch_bounds__(256)
void conv_v_kernel(const float* __restrict__ proj, const float* __restrict__ conv_w,
                   float* __restrict__ vo)
{
    int idx = blockIdx.x * blockDim.x + threadIdx.x;   // BT*VD exact
    int cv = idx & (VD - 1);
    int bt = idx >> 11;
    int t  = bt & (TT - 1);
    int ch = 2 * KD + cv;
    float acc = 0.f;
#pragma unroll
    for (int kk = 0; kk < KSZ; kk++) {
        int tt = t - 3 + kk;
        float xv = (tt >= 0) ? proj[(size_t)(bt - 3 + kk) * IPD + ch] : 0.f;
        acc = fmaf(xv, conv_w[ch * KSZ + kk], acc);
    }
    vo[idx] = silu_f(acc);
}

// ============ delta-rule recurrence ============
// one CTA per (b,h); 128 threads, thread j owns state column j (64 fp32 = 32 f32x2)
__global__ __launch_bounds__(128)
void recur_kernel(const float* __restrict__ qarr, const float* __restrict__ karr,
                  const float* __restrict__ varr, const float* __restrict__ garr,
                  const float* __restrict__ barr, float* __restrict__ oarr)
{
    const int b  = blockIdx.x >> 4;
    const int h  = blockIdx.x & 15;
    const int kh = h >> 1;             // q/k heads repeated x2
    const int j  = threadIdx.x;

    __shared__ __align__(16) float ks[2][DK];
    __shared__ __align__(16) float qs[2][DK];
    __shared__ float sc[2][2];         // [eg, beta]

    unsigned long long S2[32];
#pragma unroll
    for (int i = 0; i < 32; i++) S2[i] = 0ull;

    const size_t btb = (size_t)b * TT;
    const float* kbase = karr + (btb * NKH + kh) * DK;   // + t*512 + i
    const float* qbase = qarr + (btb * NKH + kh) * DK;
    const float* vbase = varr + btb * VD + h * DV + j;   // + t*2048
    const float* gbase = garr + btb * NVH + h;           // + t*16
    const float* bbase = barr + btb * NVH + h;
    float*       obase = oarr + btb * VD + h * DV + j;

    // prologue: stage t=0
    {
        float ldkq = (j < DK) ? kbase[j] : qbase[j - DK];
        if (j < DK) ks[0][j] = ldkq; else qs[0][j - DK] = ldkq;
        if (j == 0) sc[0][0] = expf(gbase[0]);
        if (j == 1) sc[0][1] = bbase[0];
    }
    float vcur = vbase[0];
    __syncthreads();

    for (int t = 0; t < TT; t++) {
        const int p = t & 1;
        // prefetch t+1
        float nk = 0.f, nv = 0.f, ng = 0.f, nb = 0.f;
        if (t + 1 < TT) {
            nk = (j < DK) ? kbase[(size_t)(t+1) * (NKH*DK) + j]
                          : qbase[(size_t)(t+1) * (NKH*DK) + (j - DK)];
            nv = vbase[(size_t)(t+1) * VD];
            if (j == 0) ng = gbase[(size_t)(t+1) * NVH];
            if (j == 1) nb = bbase[(size_t)(t+1) * NVH];
        }

        const float eg   = sc[p][0];
        const float beta = sc[p][1];
        const unsigned long long eg2 = pack2(eg, eg);
        const unsigned long long* k2 = (const unsigned long long*)ks[p];
        const unsigned long long* q2 = (const unsigned long long*)qs[p];

        // S <- S*eg ; dk = sum_k S[k]*kappa[k]
        unsigned long long dk2[4] = {0ull,0ull,0ull,0ull};
#pragma unroll
        for (int i = 0; i < 32; i++) {
            fmul2(S2[i], S2[i], eg2);
            ffma2(dk2[i & 3], S2[i], k2[i]);
        }
        fadd2(dk2[0], dk2[0], dk2[1]);
        fadd2(dk2[2], dk2[2], dk2[3]);
        fadd2(dk2[0], dk2[0], dk2[2]);
        float dk = lo2(dk2[0]) + hi2(dk2[0]);

        float delta = beta * (vcur - dk);
        const unsigned long long d2 = pack2(delta, delta);

        // S <- S + kappa*delta ; out = sum_k S[k]*q[k]
        unsigned long long o2[4] = {0ull,0ull,0ull,0ull};
#pragma unroll
        for (int i = 0; i < 32; i++) {
            ffma2(S2[i], k2[i], d2);
            ffma2(o2[i & 3], S2[i], q2[i]);
        }
        fadd2(o2[0], o2[0], o2[1]);
        fadd2(o2[2], o2[2], o2[3]);
        fadd2(o2[0], o2[0], o2[2]);
        obase[(size_t)t * VD] = (lo2(o2[0]) + hi2(o2[0])) * SCALE;

        // stage t+1 into the other buffer
        if (t + 1 < TT) {
            if (j < DK) ks[p ^ 1][j] = nk; else qs[p ^ 1][j - DK] = nk;
            if (j == 0) sc[p ^ 1][0] = expf(ng);
            if (j == 1) sc[p ^ 1][1] = nb;
        }
        vcur = nv;
        __syncthreads();
    }
}

// ============ RMSNorm * silu(z) gate ============
// one warp per (b,t,h); 256 threads/block
__global__ __launch_bounds__(256)
void gate_kernel(const float* __restrict__ o, const float* __restrict__ proj,
                 const float* __restrict__ nw, float* __restrict__ gated)
{
    int gw = (blockIdx.x * blockDim.x + threadIdx.x) >> 5;   // (bt,h)
    int lane = threadIdx.x & 31;
    int h  = gw & 15;
    int bt = gw >> 4;

    const float* orow = o + (size_t)bt * VD + h * DV;
    float v[4]; float ss = 0.f;
#pragma unroll
    for (int s = 0; s < 4; s++) { v[s] = orow[lane + 32 * s]; ss = fmaf(v[s], v[s], ss); }
#pragma unroll
    for (int m = 16; m; m >>= 1) ss += __shfl_xor_sync(0xffffffffu, ss, m);
    float rstd = rsqrtf(ss * (1.f / DV) + EPSR);

#pragma unroll
    for (int s = 0; s < 4; s++) {
        int dv = lane + 32 * s;
        float z = proj[(size_t)bt * IPD + CD + h * DV + dv];
        gated[(size_t)bt * VD + h * DV + dv] = nw[dv] * v[s] * rstd * silu_f(z);
    }
}

// ---------------- launch ----------------
extern "C" void kernel_launch(void* const* d_in, const int* in_sizes, int n_in,
                              void* d_out, int out_size)
{
    const float* x          = (const float*)d_in[0];
    // d_in[1] = input_pos (unused by reference)
    const float* in_proj_w  = (const float*)d_in[2];
    const float* conv_w     = (const float*)d_in[3];
    const float* dt_bias    = (const float*)d_in[4];
    const float* A_log      = (const float*)d_in[5];
    const float* norm_w     = (const float*)d_in[6];
    const float* out_proj_w = (const float*)d_in[7];
    float* out = (float*)d_out;

    float *proj, *q, *k, *v, *beta, *gdec, *o, *gate;
    cudaGetSymbolAddress((void**)&proj, g_proj);
    cudaGetSymbolAddress((void**)&q,    g_q);
    cudaGetSymbolAddress((void**)&k,    g_k);
    cudaGetSymbolAddress((void**)&v,    g_v);
    cudaGetSymbolAddress((void**)&beta, g_beta);
    cudaGetSymbolAddress((void**)&gdec, g_gdec);
    cudaGetSymbolAddress((void**)&o,    g_o);
    cudaGetSymbolAddress((void**)&gate, g_gate);

    // 1) in_proj: proj[BT, IPD] = x[BT, HID] @ W^T
    sgemm_nt_kernel<<<dim3((IPD + GTN - 1) / GTN, BT / GTM), 256>>>(x, in_proj_w, proj, BT, IPD, HID);

    // 2) conv + activations
    conv_qk_kernel<<<BT, 512>>>(proj, conv_w, A_log, dt_bias, q, k, beta, gdec);
    conv_v_kernel<<<(BT * VD) / 256, 256>>>(proj, conv_w, v);

    // 3) recurrence
    recur_kernel<<<BB * NVH, 128>>>(q, k, v, gdec, beta, o);

    // 4) norm/gate + out_proj
    gate_kernel<<<(BT * NVH) / 8, 256>>>(o, proj, norm_w, gate);
    sgemm_nt_kernel<<<dim3(HID / GTN, BT / GTM), 256>>>(gate, out_proj_w, out, BT, HID, VD);
}

// round 4
// speedup vs baseline: 1.0374x; 1.0374x over previous
#include <cuda_runtime.h>
#include <cuda_bf16.h>
#include <math.h>

// ---------------- problem constants ----------------
#define BB   2
#define TT   1024
#define HID  2048
#define NKH  8
#define NVH  16
#define DK   64
#define DV   128
#define KSZ  4
#define KD   (NKH*DK)          // 512
#define VD   (NVH*DV)          // 2048
#define CD   (2*KD + VD)       // 3072
#define IPD  (CD + VD + 2*NVH) // 5152
#define BT   (BB*TT)           // 2048
#define EPSR 1e-6f
#define SCALE 0.125f           // DK^-0.5

// ---------------- scratch (__device__ globals; no allocs allowed) ----------------
__device__ float g_proj [(size_t)BT * IPD];
__device__ float g_q    [(size_t)BT * KD];
__device__ float g_k    [(size_t)BT * KD];
__device__ float g_v    [(size_t)BT * VD];
__device__ float g_beta [(size_t)BT * NVH];
__device__ float g_gdec [(size_t)BT * NVH];
__device__ float g_o    [(size_t)BT * VD];
__device__ float g_gate [(size_t)BT * VD];

// ---------------- f32x2 packed helpers ----------------
__device__ __forceinline__ unsigned long long pack2(float lo, float hi) {
    unsigned long long r;
    asm("mov.b64 %0, {%1, %2};" : "=l"(r) : "f"(lo), "f"(hi));
    return r;
}
__device__ __forceinline__ void ffma2(unsigned long long &d, unsigned long long a, unsigned long long b) {
    asm("fma.rn.f32x2 %0, %1, %2, %0;" : "+l"(d) : "l"(a), "l"(b));
}
__device__ __forceinline__ void fmul2(unsigned long long &d, unsigned long long a, unsigned long long b) {
    asm("mul.rn.f32x2 %0, %1, %2;" : "=l"(d) : "l"(a), "l"(b));
}
__device__ __forceinline__ void fadd2(unsigned long long &d, unsigned long long a, unsigned long long b) {
    asm("add.rn.f32x2 %0, %1, %2;" : "=l"(d) : "l"(a), "l"(b));
}
__device__ __forceinline__ float lo2(unsigned long long v) { return __uint_as_float((unsigned)(v & 0xffffffffull)); }
__device__ __forceinline__ float hi2(unsigned long long v) { return __uint_as_float((unsigned)(v >> 32)); }

__device__ __forceinline__ float silu_f(float x) { return x / (1.f + expf(-x)); }

// ================= GEMM: C[M,N] = A[M,K] * B[N,K]^T, double-buffered ========
#define GTM 128
#define GTN 128
#define GTK 16

__global__ __launch_bounds__(256)
void sgemm_nt_kernel(const float* __restrict__ A, const float* __restrict__ Bw,
                     float* __restrict__ C, int M, int N, int K)
{
    __shared__ __align__(16) float As[2][GTK][GTM + 4];
    __shared__ __align__(16) float Bs[2][GTK][GTN + 4];

    const int tid = threadIdx.x;
    const int bm = blockIdx.y * GTM;
    const int bn = blockIdx.x * GTN;
    const int tx = tid & 15, ty = tid >> 4;
    const int m0 = ty * 8, n0 = tx * 8;

    unsigned long long c2[4][8];
#pragma unroll
    for (int i = 0; i < 4; i++)
#pragma unroll
        for (int j = 0; j < 8; j++) c2[i][j] = 0ull;

    const int r0 = tid >> 2;           // 0..63
    const int r1 = r0 + 64;            // 64..127
    const int kq = (tid & 3) * 4;      // 0,4,8,12

    const float* Ap0 = A + (size_t)(bm + r0) * K + kq;
    const float* Ap1 = A + (size_t)(bm + r1) * K + kq;
    const bool bv0 = (bn + r0) < N;
    const bool bv1 = (bn + r1) < N;
    const float* Bp0 = Bw + (size_t)(bn + (bv0 ? r0 : 0)) * K + kq;
    const float* Bp1 = Bw + (size_t)(bn + (bv1 ? r1 : 0)) * K + kq;

    const int ntiles = K / GTK;
    float4 a0, a1, b0, b1;

    // prologue: load tile 0
    a0 = *(const float4*)(Ap0);
    a1 = *(const float4*)(Ap1);
    b0 = bv0 ? *(const float4*)(Bp0) : make_float4(0.f,0.f,0.f,0.f);
    b1 = bv1 ? *(const float4*)(Bp1) : make_float4(0.f,0.f,0.f,0.f);
    {
        As[0][kq+0][r0]=a0.x; As[0][kq+1][r0]=a0.y; As[0][kq+2][r0]=a0.z; As[0][kq+3][r0]=a0.w;
        As[0][kq+0][r1]=a1.x; As[0][kq+1][r1]=a1.y; As[0][kq+2][r1]=a1.z; As[0][kq+3][r1]=a1.w;
        Bs[0][kq+0][r0]=b0.x; Bs[0][kq+1][r0]=b0.y; Bs[0][kq+2][r0]=b0.z; Bs[0][kq+3][r0]=b0.w;
        Bs[0][kq+0][r1]=b1.x; Bs[0][kq+1][r1]=b1.y; Bs[0][kq+2][r1]=b1.z; Bs[0][kq+3][r1]=b1.w;
    }
    __syncthreads();

    int p = 0;
    for (int kt = 0; kt < ntiles; kt++) {
        // prefetch next tile into registers
        if (kt + 1 < ntiles) {
            int off = (kt + 1) * GTK;
            a0 = *(const float4*)(Ap0 + off);
            a1 = *(const float4*)(Ap1 + off);
            b0 = bv0 ? *(const float4*)(Bp0 + off) : make_float4(0.f,0.f,0.f,0.f);
            b1 = bv1 ? *(const float4*)(Bp1 + off) : make_float4(0.f,0.f,0.f,0.f);
        }
        // compute on buffer p
#pragma unroll
        for (int kk = 0; kk < GTK; kk++) {
            unsigned long long a2[4];
            const unsigned long long* ap = (const unsigned long long*)&As[p][kk][m0];
            a2[0]=ap[0]; a2[1]=ap[1]; a2[2]=ap[2]; a2[3]=ap[3];
            float4 blo = *(const float4*)&Bs[p][kk][n0];
            float4 bhi = *(const float4*)&Bs[p][kk][n0 + 4];
            unsigned long long bb2[8];
            bb2[0]=pack2(blo.x,blo.x); bb2[1]=pack2(blo.y,blo.y);
            bb2[2]=pack2(blo.z,blo.z); bb2[3]=pack2(blo.w,blo.w);
            bb2[4]=pack2(bhi.x,bhi.x); bb2[5]=pack2(bhi.y,bhi.y);
            bb2[6]=pack2(bhi.z,bhi.z); bb2[7]=pack2(bhi.w,bhi.w);
#pragma unroll
            for (int i = 0; i < 4; i++)
#pragma unroll
                for (int j = 0; j < 8; j++)
                    ffma2(c2[i][j], a2[i], bb2[j]);
        }
        // store staged tile
        if (kt + 1 < ntiles) {
            int q = p ^ 1;
            As[q][kq+0][r0]=a0.x; As[q][kq+1][r0]=a0.y; As[q][kq+2][r0]=a0.z; As[q][kq+3][r0]=a0.w;
            As[q][kq+0][r1]=a1.x; As[q][kq+1][r1]=a1.y; As[q][kq+2][r1]=a1.z; As[q][kq+3][r1]=a1.w;
            Bs[q][kq+0][r0]=b0.x; Bs[q][kq+1][r0]=b0.y; Bs[q][kq+2][r0]=b0.z; Bs[q][kq+3][r0]=b0.w;
            Bs[q][kq+0][r1]=b1.x; Bs[q][kq+1][r1]=b1.y; Bs[q][kq+2][r1]=b1.z; Bs[q][kq+3][r1]=b1.w;
        }
        __syncthreads();
        p ^= 1;
    }

    // ---- epilogue ----
#pragma unroll
    for (int i = 0; i < 4; i++) {
        int mA = bm + m0 + 2 * i;
        int n  = bn + n0;
        float lo[8], hi[8];
#pragma unroll
        for (int j = 0; j < 8; j++) { lo[j] = lo2(c2[i][j]); hi[j] = hi2(c2[i][j]); }
        if (n + 7 < N) {
            *(float4*)(C + (size_t)mA * N + n)         = make_float4(lo[0],lo[1],lo[2],lo[3]);
            *(float4*)(C + (size_t)mA * N + n + 4)     = make_float4(lo[4],lo[5],lo[6],lo[7]);
            *(float4*)(C + (size_t)(mA+1) * N + n)     = make_float4(hi[0],hi[1],hi[2],hi[3]);
            *(float4*)(C + (size_t)(mA+1) * N + n + 4) = make_float4(hi[4],hi[5],hi[6],hi[7]);
        } else {
#pragma unroll
            for (int j = 0; j < 8; j++) {
                if (n + j < N) {
                    C[(size_t)mA * N + n + j]     = lo[j];
                    C[(size_t)(mA+1) * N + n + j] = hi[j];
                }
            }
        }
    }
}

// ============ conv(q,k) + silu + l2norm, and beta/g scalars ============
__global__ __launch_bounds__(512)
void conv_qk_kernel(const float* __restrict__ proj, const float* __restrict__ conv_w,
                    const float* __restrict__ A_log, const float* __restrict__ dt_bias,
                    float* __restrict__ qo, float* __restrict__ ko,
                    float* __restrict__ beta_o, float* __restrict__ g_o)
{
    const int bt = blockIdx.x;
    const int t  = bt & (TT - 1);
    const int warp = threadIdx.x >> 5, lane = threadIdx.x & 31;

    float r[2];
#pragma unroll
    for (int s = 0; s < 2; s++) {
        int ch = warp * 64 + s * 32 + lane;
        float acc = 0.f;
#pragma unroll
        for (int kk = 0; kk < KSZ; kk++) {
            int tt = t - 3 + kk;
            float xv = (tt >= 0) ? proj[(size_t)(bt - 3 + kk) * IPD + ch] : 0.f;
            acc = fmaf(xv, conv_w[ch * KSZ + kk], acc);
        }
        r[s] = silu_f(acc);
    }
    float ss = r[0]*r[0] + r[1]*r[1];
#pragma unroll
    for (int o = 16; o; o >>= 1) ss += __shfl_xor_sync(0xffffffffu, ss, o);
    float inv = 1.f / fmaxf(sqrtf(ss), 1e-12f);

    if (warp < 8) {
        float* dst = qo + ((size_t)bt * NKH + warp) * DK;
        dst[lane] = r[0] * inv; dst[lane + 32] = r[1] * inv;
    } else {
        float* dst = ko + ((size_t)bt * NKH + (warp - 8)) * DK;
        dst[lane] = r[0] * inv; dst[lane + 32] = r[1] * inv;
    }

    if (threadIdx.x < NVH) {
        int h = threadIdx.x;
        float braw = proj[(size_t)bt * IPD + CD + VD + h];
        float araw = proj[(size_t)bt * IPD + CD + VD + NVH + h];
        beta_o[bt * NVH + h] = 1.f / (1.f + expf(-braw));
        float si = araw + dt_bias[h];
        float sp = (si > 20.f) ? si : log1pf(expf(si));
        g_o[bt * NVH + h] = -expf(A_log[h]) * sp;
    }
}

// ============ conv(v) + silu ============
__global__ __launch_bounds__(256)
void conv_v_kernel(const float* __restrict__ proj, const float* __restrict__ conv_w,
                   float* __restrict__ vo)
{
    int idx = blockIdx.x * blockDim.x + threadIdx.x;
    int cv = idx & (VD - 1);
    int bt = idx >> 11;
    int t  = bt & (TT - 1);
    int ch = 2 * KD + cv;
    float acc = 0.f;
#pragma unroll
    for (int kk = 0; kk < KSZ; kk++) {
        int tt = t - 3 + kk;
        float xv = (tt >= 0) ? proj[(size_t)(bt - 3 + kk) * IPD + ch] : 0.f;
        acc = fmaf(xv, conv_w[ch * KSZ + kk], acc);
    }
    vo[idx] = silu_f(acc);
}

// ============ delta-rule recurrence, v2 ============
// grid = BB*NVH*4 = 128 CTAs; 64 threads (2 warps) per CTA.
// CTA handles (b, h, 32-column group). Lane pair (2c, 2c+1) owns column c:
// lane 2c   holds state rows k=[0,32)  for that column (16 f32x2 regs)
// lane 2c+1 holds state rows k=[32,64)
// dk / out reduced via shfl.bfly(1). k/q/v/scalars double-buffered in smem.
#define RCOLS 32

__global__ __launch_bounds__(64)
void recur_kernel(const float* __restrict__ qarr, const float* __restrict__ karr,
                  const float* __restrict__ varr, const float* __restrict__ garr,
                  const float* __restrict__ barr, float* __restrict__ oarr)
{
    const int cta = blockIdx.x;
    const int cg  = cta & 3;
    const int h   = (cta >> 2) & 15;
    const int b   = cta >> 6;
    const int kh  = h >> 1;
    const int j    = threadIdx.x;     // 0..63
    const int col  = (j >> 1);        // 0..31 (within group)
    const int half = j & 1;

    // padded so the two half-groups' broadcast reads hit disjoint banks
    __shared__ __align__(16) float ks[2][DK + 2];
    __shared__ __align__(16) float qs[2][DK + 2];
    __shared__ float vs[2][RCOLS];
    __shared__ float sc[2][2];        // [eg, beta]

    unsigned long long S2[16];
#pragma unroll
    for (int i = 0; i < 16; i++) S2[i] = 0ull;

    const size_t btb = (size_t)b * TT;
    const float* kbase = karr + (btb * NKH + kh) * DK;       // + t*512 + j
    const float* qbase = qarr + (btb * NKH + kh) * DK;
    const float* vbase = varr + btb * VD + h * DV + cg * RCOLS; // + t*2048 + lane
    const float* gbase = garr + btb * NVH + h;               // + t*16
    const float* bbase = barr + btb * NVH + h;
    float*       obase = oarr + btb * VD + h * DV + cg * RCOLS + col;

    const int wj = (j < 32) ? j : (j + 2);   // padded store index

    // prologue: stage t=0
    ks[0][wj] = kbase[j];
    qs[0][wj] = qbase[j];
    if (j < RCOLS) vs[0][j] = vbase[j];
    if (j == 0) sc[0][0] = expf(gbase[0]);
    if (j == 1) sc[0][1] = bbase[0];
    __syncthreads();

    for (int t = 0; t < TT; t++) {
        const int p = t & 1;

        // prefetch t+1 (issue loads early)
        float nk = 0.f, nq = 0.f, nv = 0.f, ng = 0.f, nb = 0.f;
        if (t + 1 < TT) {
            nk = kbase[(size_t)(t+1) * (NKH*DK) + j];
            nq = qbase[(size_t)(t+1) * (NKH*DK) + j];
            if (j < RCOLS) nv = vbase[(size_t)(t+1) * VD + j];
            if (j == 0) ng = gbase[(size_t)(t+1) * NVH];
            if (j == 1) nb = bbase[(size_t)(t+1) * NVH];
        }

        const float eg   = sc[p][0];
        const float beta = sc[p][1];
        const unsigned long long eg2 = pack2(eg, eg);
        const unsigned long long* k2 = (const unsigned long long*)ks[p] + half * 17;
        const unsigned long long* q2 = (const unsigned long long*)qs[p] + half * 17;

        // S <- S*eg ; dk_half = sum over this half's 32 rows of S*k
        unsigned long long dk2[4] = {0ull,0ull,0ull,0ull};
#pragma unroll
        for (int i = 0; i < 16; i++) {
            fmul2(S2[i], S2[i], eg2);
            ffma2(dk2[i & 3], S2[i], k2[i]);
        }
        fadd2(dk2[0], dk2[0], dk2[1]);
        fadd2(dk2[2], dk2[2], dk2[3]);
        fadd2(dk2[0], dk2[0], dk2[2]);
        float dkh = lo2(dk2[0]) + hi2(dk2[0]);
        dkh += __shfl_xor_sync(0xffffffffu, dkh, 1);

        float delta = beta * (vs[p][col] - dkh);
        const unsigned long long d2 = pack2(delta, delta);

        // S <- S + k*delta ; out_half = sum S*q
        unsigned long long o2[4] = {0ull,0ull,0ull,0ull};
#pragma unroll
        for (int i = 0; i < 16; i++) {
            ffma2(S2[i], k2[i], d2);
            ffma2(o2[i & 3], S2[i], q2[i]);
        }
        fadd2(o2[0], o2[0], o2[1]);
        fadd2(o2[2], o2[2], o2[3]);
        fadd2(o2[0], o2[0], o2[2]);
        float oh = lo2(o2[0]) + hi2(o2[0]);
        oh += __shfl_xor_sync(0xffffffffu, oh, 1);
        if (half == 0) obase[(size_t)t * VD] = oh * SCALE;

        // stage t+1 into the other buffer
        if (t + 1 < TT) {
            const int pn = p ^ 1;
            ks[pn][wj] = nk;
            qs[pn][wj] = nq;
            if (j < RCOLS) vs[pn][j] = nv;
            if (j == 0) sc[pn][0] = expf(ng);
            if (j == 1) sc[pn][1] = nb;
        }
        __syncthreads();
    }
}

// ============ RMSNorm * silu(z) gate ============
__global__ __launch_bounds__(256)
void gate_kernel(const float* __restrict__ o, const float* __restrict__ proj,
                 const float* __restrict__ nw, float* __restrict__ gated)
{
    int gw = (blockIdx.x * blockDim.x + threadIdx.x) >> 5;
    int lane = threadIdx.x & 31;
    int h  = gw & 15;
    int bt = gw >> 4;

    const float* orow = o + (size_t)bt * VD + h * DV;
    float v[4]; float ss = 0.f;
#pragma unroll
    for (int s = 0; s < 4; s++) { v[s] = orow[lane + 32 * s]; ss = fmaf(v[s], v[s], ss); }
#pragma unroll
    for (int m = 16; m; m >>= 1) ss += __shfl_xor_sync(0xffffffffu, ss, m);
    float rstd = rsqrtf(ss * (1.f / DV) + EPSR);

#pragma unroll
    for (int s = 0; s < 4; s++) {
        int dv = lane + 32 * s;
        float z = proj[(size_t)bt * IPD + CD + h * DV + dv];
        gated[(size_t)bt * VD + h * DV + dv] = nw[dv] * v[s] * rstd * silu_f(z);
    }
}

// ---------------- launch ----------------
extern "C" void kernel_launch(void* const* d_in, const int* in_sizes, int n_in,
                              void* d_out, int out_size)
{
    const float* x          = (const float*)d_in[0];
    const float* in_proj_w  = (const float*)d_in[2];
    const float* conv_w     = (const float*)d_in[3];
    const float* dt_bias    = (const float*)d_in[4];
    const float* A_log      = (const float*)d_in[5];
    const float* norm_w     = (const float*)d_in[6];
    const float* out_proj_w = (const float*)d_in[7];
    float* out = (float*)d_out;

    float *proj, *q, *k, *v, *beta, *gdec, *o, *gate;
    cudaGetSymbolAddress((void**)&proj, g_proj);
    cudaGetSymbolAddress((void**)&q,    g_q);
    cudaGetSymbolAddress((void**)&k,    g_k);
    cudaGetSymbolAddress((void**)&v,    g_v);
    cudaGetSymbolAddress((void**)&beta, g_beta);
    cudaGetSymbolAddress((void**)&gdec, g_gdec);
    cudaGetSymbolAddress((void**)&o,    g_o);
    cudaGetSymbolAddress((void**)&gate, g_gate);

    sgemm_nt_kernel<<<dim3((IPD + GTN - 1) / GTN, BT / GTM), 256>>>(x, in_proj_w, proj, BT, IPD, HID);

    conv_qk_kernel<<<BT, 512>>>(proj, conv_w, A_log, dt_bias, q, k, beta, gdec);
    conv_v_kernel<<<(BT * VD) / 256, 256>>>(proj, conv_w, v);

    recur_kernel<<<BB * NVH * 4, 64>>>(q, k, v, gdec, beta, o);

    gate_kernel<<<(BT * NVH) / 8, 256>>>(o, proj, norm_w, gate);
    sgemm_nt_kernel<<<dim3(HID / GTN, BT / GTM), 256>>>(gate, out_proj_w, out, BT, HID, VD);
}

// round 5
// speedup vs baseline: 1.0782x; 1.0394x over previous
#include <cuda_runtime.h>
#include <cuda_bf16.h>
#include <math.h>

// ---------------- problem constants ----------------
#define BB   2
#define TT   1024
#define HID  2048
#define NKH  8
#define NVH  16
#define DK   64
#define DV   128
#define KSZ  4
#define KD   (NKH*DK)          // 512
#define VD   (NVH*DV)          // 2048
#define CD   (2*KD + VD)       // 3072
#define IPD  (CD + VD + 2*NVH) // 5152
#define BT   (BB*TT)           // 2048
#define EPSR 1e-6f
#define SCALE 0.125f           // DK^-0.5

// ---------------- scratch (__device__ globals; no allocs allowed) ----------------
__device__ float g_proj [(size_t)BT * IPD];
__device__ float g_q    [(size_t)BT * KD];
__device__ float g_k    [(size_t)BT * KD];
__device__ float g_v    [(size_t)BT * VD];
__device__ float g_beta [(size_t)BT * NVH];
__device__ float g_gdec [(size_t)BT * NVH];
__device__ float g_o    [(size_t)BT * VD];
__device__ float g_gate [(size_t)BT * VD];

// ---------------- f32x2 packed helpers ----------------
__device__ __forceinline__ unsigned long long pack2(float lo, float hi) {
    unsigned long long r;
    asm("mov.b64 %0, {%1, %2};" : "=l"(r) : "f"(lo), "f"(hi));
    return r;
}
__device__ __forceinline__ void ffma2(unsigned long long &d, unsigned long long a, unsigned long long b) {
    asm("fma.rn.f32x2 %0, %1, %2, %0;" : "+l"(d) : "l"(a), "l"(b));
}
__device__ __forceinline__ void fmul2(unsigned long long &d, unsigned long long a, unsigned long long b) {
    asm("mul.rn.f32x2 %0, %1, %2;" : "=l"(d) : "l"(a), "l"(b));
}
__device__ __forceinline__ void fadd2(unsigned long long &d, unsigned long long a, unsigned long long b) {
    asm("add.rn.f32x2 %0, %1, %2;" : "=l"(d) : "l"(a), "l"(b));
}
__device__ __forceinline__ float lo2(unsigned long long v) { return __uint_as_float((unsigned)(v & 0xffffffffull)); }
__device__ __forceinline__ float hi2(unsigned long long v) { return __uint_as_float((unsigned)(v >> 32)); }

__device__ __forceinline__ float silu_f(float x) { return x / (1.f + expf(-x)); }

// ================= GEMM: C[M,N] = A[M,K] * B[N,K]^T, double-buffered ========
#define GTM 128
#define GTN 128
#define GTK 16

__global__ __launch_bounds__(256)
void sgemm_nt_kernel(const float* __restrict__ A, const float* __restrict__ Bw,
                     float* __restrict__ C, int M, int N, int K)
{
    __shared__ __align__(16) float As[2][GTK][GTM + 4];
    __shared__ __align__(16) float Bs[2][GTK][GTN + 4];

    const int tid = threadIdx.x;
    const int bm = blockIdx.y * GTM;
    const int bn = blockIdx.x * GTN;
    const int tx = tid & 15, ty = tid >> 4;
    const int m0 = ty * 8, n0 = tx * 8;

    unsigned long long c2[4][8];
#pragma unroll
    for (int i = 0; i < 4; i++)
#pragma unroll
        for (int j = 0; j < 8; j++) c2[i][j] = 0ull;

    const int r0 = tid >> 2;           // 0..63
    const int r1 = r0 + 64;            // 64..127
    const int kq = (tid & 3) * 4;      // 0,4,8,12

    const float* Ap0 = A + (size_t)(bm + r0) * K + kq;
    const float* Ap1 = A + (size_t)(bm + r1) * K + kq;
    const bool bv0 = (bn + r0) < N;
    const bool bv1 = (bn + r1) < N;
    const float* Bp0 = Bw + (size_t)(bn + (bv0 ? r0 : 0)) * K + kq;
    const float* Bp1 = Bw + (size_t)(bn + (bv1 ? r1 : 0)) * K + kq;

    const int ntiles = K / GTK;
    float4 a0, a1, b0, b1;

    a0 = *(const float4*)(Ap0);
    a1 = *(const float4*)(Ap1);
    b0 = bv0 ? *(const float4*)(Bp0) : make_float4(0.f,0.f,0.f,0.f);
    b1 = bv1 ? *(const float4*)(Bp1) : make_float4(0.f,0.f,0.f,0.f);
    {
        As[0][kq+0][r0]=a0.x; As[0][kq+1][r0]=a0.y; As[0][kq+2][r0]=a0.z; As[0][kq+3][r0]=a0.w;
        As[0][kq+0][r1]=a1.x; As[0][kq+1][r1]=a1.y; As[0][kq+2][r1]=a1.z; As[0][kq+3][r1]=a1.w;
        Bs[0][kq+0][r0]=b0.x; Bs[0][kq+1][r0]=b0.y; Bs[0][kq+2][r0]=b0.z; Bs[0][kq+3][r0]=b0.w;
        Bs[0][kq+0][r1]=b1.x; Bs[0][kq+1][r1]=b1.y; Bs[0][kq+2][r1]=b1.z; Bs[0][kq+3][r1]=b1.w;
    }
    __syncthreads();

    int p = 0;
    for (int kt = 0; kt < ntiles; kt++) {
        if (kt + 1 < ntiles) {
            int off = (kt + 1) * GTK;
            a0 = *(const float4*)(Ap0 + off);
            a1 = *(const float4*)(Ap1 + off);
            b0 = bv0 ? *(const float4*)(Bp0 + off) : make_float4(0.f,0.f,0.f,0.f);
            b1 = bv1 ? *(const float4*)(Bp1 + off) : make_float4(0.f,0.f,0.f,0.f);
        }
#pragma unroll
        for (int kk = 0; kk < GTK; kk++) {
            unsigned long long a2[4];
            const unsigned long long* ap = (const unsigned long long*)&As[p][kk][m0];
            a2[0]=ap[0]; a2[1]=ap[1]; a2[2]=ap[2]; a2[3]=ap[3];
            float4 blo = *(const float4*)&Bs[p][kk][n0];
            float4 bhi = *(const float4*)&Bs[p][kk][n0 + 4];
            unsigned long long bb2[8];
            bb2[0]=pack2(blo.x,blo.x); bb2[1]=pack2(blo.y,blo.y);
            bb2[2]=pack2(blo.z,blo.z); bb2[3]=pack2(blo.w,blo.w);
            bb2[4]=pack2(bhi.x,bhi.x); bb2[5]=pack2(bhi.y,bhi.y);
            bb2[6]=pack2(bhi.z,bhi.z); bb2[7]=pack2(bhi.w,bhi.w);
#pragma unroll
            for (int i = 0; i < 4; i++)
#pragma unroll
                for (int j = 0; j < 8; j++)
                    ffma2(c2[i][j], a2[i], bb2[j]);
        }
        if (kt + 1 < ntiles) {
            int q = p ^ 1;
            As[q][kq+0][r0]=a0.x; As[q][kq+1][r0]=a0.y; As[q][kq+2][r0]=a0.z; As[q][kq+3][r0]=a0.w;
            As[q][kq+0][r1]=a1.x; As[q][kq+1][r1]=a1.y; As[q][kq+2][r1]=a1.z; As[q][kq+3][r1]=a1.w;
            Bs[q][kq+0][r0]=b0.x; Bs[q][kq+1][r0]=b0.y; Bs[q][kq+2][r0]=b0.z; Bs[q][kq+3][r0]=b0.w;
            Bs[q][kq+0][r1]=b1.x; Bs[q][kq+1][r1]=b1.y; Bs[q][kq+2][r1]=b1.z; Bs[q][kq+3][r1]=b1.w;
        }
        __syncthreads();
        p ^= 1;
    }

#pragma unroll
    for (int i = 0; i < 4; i++) {
        int mA = bm + m0 + 2 * i;
        int n  = bn + n0;
        float lo[8], hi[8];
#pragma unroll
        for (int j = 0; j < 8; j++) { lo[j] = lo2(c2[i][j]); hi[j] = hi2(c2[i][j]); }
        if (n + 7 < N) {
            *(float4*)(C + (size_t)mA * N + n)         = make_float4(lo[0],lo[1],lo[2],lo[3]);
            *(float4*)(C + (size_t)mA * N + n + 4)     = make_float4(lo[4],lo[5],lo[6],lo[7]);
            *(float4*)(C + (size_t)(mA+1) * N + n)     = make_float4(hi[0],hi[1],hi[2],hi[3]);
            *(float4*)(C + (size_t)(mA+1) * N + n + 4) = make_float4(hi[4],hi[5],hi[6],hi[7]);
        } else {
#pragma unroll
            for (int j = 0; j < 8; j++) {
                if (n + j < N) {
                    C[(size_t)mA * N + n + j]     = lo[j];
                    C[(size_t)(mA+1) * N + n + j] = hi[j];
                }
            }
        }
    }
}

// ============ conv(q,k) + silu + l2norm, and beta/g scalars ============
__global__ __launch_bounds__(512)
void conv_qk_kernel(const float* __restrict__ proj, const float* __restrict__ conv_w,
                    const float* __restrict__ A_log, const float* __restrict__ dt_bias,
                    float* __restrict__ qo, float* __restrict__ ko,
                    float* __restrict__ beta_o, float* __restrict__ g_o)
{
    const int bt = blockIdx.x;
    const int t  = bt & (TT - 1);
    const int warp = threadIdx.x >> 5, lane = threadIdx.x & 31;

    float r[2];
#pragma unroll
    for (int s = 0; s < 2; s++) {
        int ch = warp * 64 + s * 32 + lane;
        float acc = 0.f;
#pragma unroll
        for (int kk = 0; kk < KSZ; kk++) {
            int tt = t - 3 + kk;
            float xv = (tt >= 0) ? proj[(size_t)(bt - 3 + kk) * IPD + ch] : 0.f;
            acc = fmaf(xv, conv_w[ch * KSZ + kk], acc);
        }
        r[s] = silu_f(acc);
    }
    float ss = r[0]*r[0] + r[1]*r[1];
#pragma unroll
    for (int o = 16; o; o >>= 1) ss += __shfl_xor_sync(0xffffffffu, ss, o);
    float inv = 1.f / fmaxf(sqrtf(ss), 1e-12f);

    if (warp < 8) {
        float* dst = qo + ((size_t)bt * NKH + warp) * DK;
        dst[lane] = r[0] * inv; dst[lane + 32] = r[1] * inv;
    } else {
        float* dst = ko + ((size_t)bt * NKH + (warp - 8)) * DK;
        dst[lane] = r[0] * inv; dst[lane + 32] = r[1] * inv;
    }

    if (threadIdx.x < NVH) {
        int h = threadIdx.x;
        float braw = proj[(size_t)bt * IPD + CD + VD + h];
        float araw = proj[(size_t)bt * IPD + CD + VD + NVH + h];
        beta_o[bt * NVH + h] = 1.f / (1.f + expf(-braw));
        float si = araw + dt_bias[h];
        float sp = (si > 20.f) ? si : log1pf(expf(si));
        g_o[bt * NVH + h] = -expf(A_log[h]) * sp;
    }
}

// ============ conv(v) + silu ============
__global__ __launch_bounds__(256)
void conv_v_kernel(const float* __restrict__ proj, const float* __restrict__ conv_w,
                   float* __restrict__ vo)
{
    int idx = blockIdx.x * blockDim.x + threadIdx.x;
    int cv = idx & (VD - 1);
    int bt = idx >> 11;
    int t  = bt & (TT - 1);
    int ch = 2 * KD + cv;
    float acc = 0.f;
#pragma unroll
    for (int kk = 0; kk < KSZ; kk++) {
        int tt = t - 3 + kk;
        float xv = (tt >= 0) ? proj[(size_t)(bt - 3 + kk) * IPD + ch] : 0.f;
        acc = fmaf(xv, conv_w[ch * KSZ + kk], acc);
    }
    vo[idx] = silu_f(acc);
}

// ============ delta-rule recurrence, v3: depth-3 load pipeline ============
// grid = BB*NVH*4 = 128 CTAs; 64 threads (2 warps).
// Lane pair (2c,2c+1) owns column c; half = lane&1 owns k-rows [half*32, half*32+32).
// Ring of 3 smem stage buffers; loads for step t+3 issued at iter t; registers
// holding step t+2 (issued at iter t-1, ~2 iters of slack) stored at iter t.
#define RCOLS 32
#define RST   3

__global__ __launch_bounds__(64)
void recur_kernel(const float* __restrict__ qarr, const float* __restrict__ karr,
                  const float* __restrict__ varr, const float* __restrict__ garr,
                  const float* __restrict__ barr, float* __restrict__ oarr)
{
    const int cta = blockIdx.x;
    const int cg  = cta & 3;
    const int h   = (cta >> 2) & 15;
    const int b   = cta >> 6;
    const int kh  = h >> 1;
    const int j    = threadIdx.x;     // 0..63
    const int col  = (j >> 1);        // 0..31
    const int half = j & 1;

    __shared__ __align__(16) float ks[RST][DK + 2];
    __shared__ __align__(16) float qs[RST][DK + 2];
    __shared__ float vs[RST][RCOLS];
    __shared__ float sc[RST][2];      // [exp(g), beta]

    unsigned long long S2[16];
#pragma unroll
    for (int i = 0; i < 16; i++) S2[i] = 0ull;

    const size_t btb = (size_t)b * TT;
    const float* kbase = karr + (btb * NKH + kh) * DK;          // + t*512 + j
    const float* qbase = qarr + (btb * NKH + kh) * DK;
    const float* vbase = varr + btb * VD + h * DV + cg * RCOLS; // + t*2048 + j
    const float* gbase = garr + btb * NVH + h;                  // + t*16
    const float* bbase = barr + btb * NVH + h;
    float*       obase = oarr + btb * VD + h * DV + cg * RCOLS + col;

    const int wj = (j < 32) ? j : (j + 2);   // bank-padded store index

    // ---- prologue: stage t=0, t=1 directly; issue loads for t=2 ----
#pragma unroll
    for (int s = 0; s < 2; s++) {
        ks[s][wj] = kbase[(size_t)s * KD + j];
        qs[s][wj] = qbase[(size_t)s * KD + j];
        if (j < RCOLS) vs[s][j] = vbase[(size_t)s * VD + j];
        if (j == 0) sc[s][0] = expf(gbase[(size_t)s * NVH]);
        if (j == 1) sc[s][1] = bbase[(size_t)s * NVH];
    }
    float Ak = kbase[(size_t)2 * KD + j];
    float Aq = qbase[(size_t)2 * KD + j];
    float Av = (j < RCOLS) ? vbase[(size_t)2 * VD + j] : 0.f;
    float Ag = (j == 0) ? gbase[(size_t)2 * NVH] : 0.f;
    float Ab = (j == 1) ? bbase[(size_t)2 * NVH] : 0.f;
    __syncthreads();

    int p = 0;            // buffer index for current step
    for (int t = 0; t < TT; t++) {
        // ---- issue loads for t+3 ----
        float Bk = 0.f, Bq = 0.f, Bv = 0.f, Bg = 0.f, Bb2v = 0.f;
        if (t + 3 < TT) {
            const size_t o3 = (size_t)(t + 3);
            Bk = kbase[o3 * KD + j];
            Bq = qbase[o3 * KD + j];
            if (j < RCOLS) Bv = vbase[o3 * VD + j];
            if (j == 0) Bg = gbase[o3 * NVH];
            if (j == 1) Bb2v = bbase[o3 * NVH];
        }

        // ---- compute on buffer p ----
        const float eg   = sc[p][0];
        const float beta = sc[p][1];
        const unsigned long long eg2 = pack2(eg, eg);
        const unsigned long long* k2 = (const unsigned long long*)ks[p] + half * 17;
        const unsigned long long* q2 = (const unsigned long long*)qs[p] + half * 17;

        unsigned long long dk2[4] = {0ull,0ull,0ull,0ull};
#pragma unroll
        for (int i = 0; i < 16; i++) {
            fmul2(S2[i], S2[i], eg2);
            ffma2(dk2[i & 3], S2[i], k2[i]);
        }
        fadd2(dk2[0], dk2[0], dk2[1]);
        fadd2(dk2[2], dk2[2], dk2[3]);
        fadd2(dk2[0], dk2[0], dk2[2]);
        float dkh = lo2(dk2[0]) + hi2(dk2[0]);
        dkh += __shfl_xor_sync(0xffffffffu, dkh, 1);

        float delta = beta * (vs[p][col] - dkh);
        const unsigned long long d2 = pack2(delta, delta);

        unsigned long long o2[4] = {0ull,0ull,0ull,0ull};
#pragma unroll
        for (int i = 0; i < 16; i++) {
            ffma2(S2[i], k2[i], d2);
            ffma2(o2[i & 3], S2[i], q2[i]);
        }
        fadd2(o2[0], o2[0], o2[1]);
        fadd2(o2[2], o2[2], o2[3]);
        fadd2(o2[0], o2[0], o2[2]);
        float oh = lo2(o2[0]) + hi2(o2[0]);
        oh += __shfl_xor_sync(0xffffffffu, oh, 1);
        if (half == 0) obase[(size_t)t * VD] = oh * SCALE;

        // ---- store regs holding t+2 into buffer (t+2)%3 ----
        if (t + 2 < TT) {
            int pn = p + 2; if (pn >= RST) pn -= RST;
            ks[pn][wj] = Ak;
            qs[pn][wj] = Aq;
            if (j < RCOLS) vs[pn][j] = Av;
            if (j == 0) sc[pn][0] = expf(Ag);
            if (j == 1) sc[pn][1] = Ab;
        }
        Ak = Bk; Aq = Bq; Av = Bv; Ag = Bg; Ab = Bb2v;

        __syncthreads();
        if (++p == RST) p = 0;
    }
}

// ============ RMSNorm * silu(z) gate ============
__global__ __launch_bounds__(256)
void gate_kernel(const float* __restrict__ o, const float* __restrict__ proj,
                 const float* __restrict__ nw, float* __restrict__ gated)
{
    int gw = (blockIdx.x * blockDim.x + threadIdx.x) >> 5;
    int lane = threadIdx.x & 31;
    int h  = gw & 15;
    int bt = gw >> 4;

    const float* orow = o + (size_t)bt * VD + h * DV;
    float v[4]; float ss = 0.f;
#pragma unroll
    for (int s = 0; s < 4; s++) { v[s] = orow[lane + 32 * s]; ss = fmaf(v[s], v[s], ss); }
#pragma unroll
    for (int m = 16; m; m >>= 1) ss += __shfl_xor_sync(0xffffffffu, ss, m);
    float rstd = rsqrtf(ss * (1.f / DV) + EPSR);

#pragma unroll
    for (int s = 0; s < 4; s++) {
        int dv = lane + 32 * s;
        float z = proj[(size_t)bt * IPD + CD + h * DV + dv];
        gated[(size_t)bt * VD + h * DV + dv] = nw[dv] * v[s] * rstd * silu_f(z);
    }
}

// ---------------- launch ----------------
extern "C" void kernel_launch(void* const* d_in, const int* in_sizes, int n_in,
                              void* d_out, int out_size)
{
    const float* x          = (const float*)d_in[0];
    const float* in_proj_w  = (const float*)d_in[2];
    const float* conv_w     = (const float*)d_in[3];
    const float* dt_bias    = (const float*)d_in[4];
    const float* A_log      = (const float*)d_in[5];
    const float* norm_w     = (const float*)d_in[6];
    const float* out_proj_w = (const float*)d_in[7];
    float* out = (float*)d_out;

    float *proj, *q, *k, *v, *beta, *gdec, *o, *gate;
    cudaGetSymbolAddress((void**)&proj, g_proj);
    cudaGetSymbolAddress((void**)&q,    g_q);
    cudaGetSymbolAddress((void**)&k,    g_k);
    cudaGetSymbolAddress((void**)&v,    g_v);
    cudaGetSymbolAddress((void**)&beta, g_beta);
    cudaGetSymbolAddress((void**)&gdec, g_gdec);
    cudaGetSymbolAddress((void**)&o,    g_o);
    cudaGetSymbolAddress((void**)&gate, g_gate);

    sgemm_nt_kernel<<<dim3((IPD + GTN - 1) / GTN, BT / GTM), 256>>>(x, in_proj_w, proj, BT, IPD, HID);

    conv_qk_kernel<<<BT, 512>>>(proj, conv_w, A_log, dt_bias, q, k, beta, gdec);
    conv_v_kernel<<<(BT * VD) / 256, 256>>>(proj, conv_w, v);

    recur_kernel<<<BB * NVH * 4, 64>>>(q, k, v, gdec, beta, o);

    gate_kernel<<<(BT * NVH) / 8, 256>>>(o, proj, norm_w, gate);
    sgemm_nt_kernel<<<dim3(HID / GTN, BT / GTM), 256>>>(gate, out_proj_w, out, BT, HID, VD);
}

// round 7
// speedup vs baseline: 1.8005x; 1.6700x over previous
#include <cuda_runtime.h>
#include <cuda_bf16.h>
#include <math.h>
#include <stdint.h>

// ---------------- problem constants ----------------
#define BB   2
#define TT   1024
#define HID  2048
#define NKH  8
#define NVH  16
#define DK   64
#define DV   128
#define KSZ  4
#define KD   (NKH*DK)          // 512
#define VD   (NVH*DV)          // 2048
#define CD   (2*KD + VD)       // 3072
#define IPD  (CD + VD + 2*NVH) // 5152
#define BT   (BB*TT)           // 2048
#define EPSR 1e-6f
#define SCALE 0.125f           // DK^-0.5

// ---------------- scratch (__device__ globals; no allocs allowed) ----------------
__device__ float g_proj [(size_t)BT * IPD];
__device__ float g_q    [(size_t)BT * KD];
__device__ float g_k    [(size_t)BT * KD];
__device__ float g_v    [(size_t)BT * VD];
__device__ float g_beta [(size_t)BT * NVH];
__device__ float g_gdec [(size_t)BT * NVH];
__device__ float g_o    [(size_t)BT * VD];

// bf16 hi/lo split operands for tensor-core GEMMs
__device__ __nv_bfloat16 g_xh [(size_t)BT * HID];
__device__ __nv_bfloat16 g_xl [(size_t)BT * HID];
__device__ __nv_bfloat16 g_wih[(size_t)IPD * HID];
__device__ __nv_bfloat16 g_wil[(size_t)IPD * HID];
__device__ __nv_bfloat16 g_woh[(size_t)HID * VD];
__device__ __nv_bfloat16 g_wol[(size_t)HID * VD];
__device__ __nv_bfloat16 g_gh [(size_t)BT * VD];
__device__ __nv_bfloat16 g_gl [(size_t)BT * VD];

// ---------------- f32x2 packed helpers ----------------
__device__ __forceinline__ unsigned long long pack2(float lo, float hi) {
    unsigned long long r;
    asm("mov.b64 %0, {%1, %2};" : "=l"(r) : "f"(lo), "f"(hi));
    return r;
}
__device__ __forceinline__ void ffma2(unsigned long long &d, unsigned long long a, unsigned long long b) {
    asm("fma.rn.f32x2 %0, %1, %2, %0;" : "+l"(d) : "l"(a), "l"(b));
}
__device__ __forceinline__ void fmul2(unsigned long long &d, unsigned long long a, unsigned long long b) {
    asm("mul.rn.f32x2 %0, %1, %2;" : "=l"(d) : "l"(a), "l"(b));
}
__device__ __forceinline__ void fadd2(unsigned long long &d, unsigned long long a, unsigned long long b) {
    asm("add.rn.f32x2 %0, %1, %2;" : "=l"(d) : "l"(a), "l"(b));
}
__device__ __forceinline__ float lo2(unsigned long long v) { return __uint_as_float((unsigned)(v & 0xffffffffull)); }
__device__ __forceinline__ float hi2(unsigned long long v) { return __uint_as_float((unsigned)(v >> 32)); }

__device__ __forceinline__ float silu_f(float x) { return x / (1.f + expf(-x)); }

// ---------------- HMMA / ldmatrix / cp.async helpers (sm_80+ ISA) ----------------
__device__ __forceinline__ uint32_t smem_u32(const void* p) {
    uint32_t a;
    asm("{ .reg .u64 t; cvta.to.shared.u64 t, %1; cvt.u32.u64 %0, t; }" : "=r"(a) : "l"(p));
    return a;
}
__device__ __forceinline__ void ldsm_x4(uint32_t* r, uint32_t addr) {
    asm volatile("ldmatrix.sync.aligned.m8n8.x4.shared.b16 {%0,%1,%2,%3}, [%4];"
        : "=r"(r[0]), "=r"(r[1]), "=r"(r[2]), "=r"(r[3]) : "r"(addr));
}
__device__ __forceinline__ void mma_bf16(float* c, const uint32_t* a, const uint32_t* b) {
    asm volatile(
        "mma.sync.aligned.m16n8k16.row.col.f32.bf16.bf16.f32 "
        "{%0,%1,%2,%3}, {%4,%5,%6,%7}, {%8,%9}, {%0,%1,%2,%3};"
        : "+f"(c[0]), "+f"(c[1]), "+f"(c[2]), "+f"(c[3])
        : "r"(a[0]), "r"(a[1]), "r"(a[2]), "r"(a[3]), "r"(b[0]), "r"(b[1]));
}
__device__ __forceinline__ void cpa16(uint32_t dst, const void* src) {
    asm volatile("cp.async.cg.shared.global [%0], [%1], 16;" :: "r"(dst), "l"(src));
}
#define CP_COMMIT() asm volatile("cp.async.commit_group;" ::: "memory")
#define CP_WAIT1()  asm volatile("cp.async.wait_group 1;" ::: "memory")

// ============ fp32 -> bf16 hi/lo split ============
__global__ __launch_bounds__(256)
void split_kernel(const float* __restrict__ in, __nv_bfloat16* __restrict__ hi,
                  __nv_bfloat16* __restrict__ lo, int n)
{
    int i = blockIdx.x * blockDim.x + threadIdx.x;
    if (i < n) {
        float x = in[i];
        __nv_bfloat16 h = __float2bfloat16(x);
        float r = x - __bfloat162float(h);
        hi[i] = h;
        lo[i] = __float2bfloat16(r);
    }
}

// ============ tensor-core GEMM: C[M,N] = A[M,K] @ B[N,K]^T (bf16 hi/lo split) ============
// tile 128x128x32, 256 threads (8 warps, warp = 32m x 64n), cp.async double buffer.
#define ROWP   40                        // smem row pitch in bf16 elems (80B, ldmatrix conflict-free)
#define ARR    (128 * ROWP * 2)          // 10240 B per matrix tile
#define OFF_AH 0
#define OFF_AL ARR
#define OFF_BH (2*ARR)
#define OFF_BL (3*ARR)
#define STG    (4*ARR)                   // 40960 B per stage
#define GSMEM  (2*STG)                   // 81920 B

__global__ __launch_bounds__(256)
void gemm_bf16split_kernel(const __nv_bfloat16* __restrict__ Ah, const __nv_bfloat16* __restrict__ Al,
                           const __nv_bfloat16* __restrict__ Bh, const __nv_bfloat16* __restrict__ Bl,
                           float* __restrict__ C, int M, int N, int K)
{
    extern __shared__ __align__(128) char smem[];
    const uint32_t sbase = smem_u32(smem);
    const int tid  = threadIdx.x;
    const int wid  = tid >> 5, lane = tid & 31;
    const int bm = blockIdx.y * 128;
    const int bn = blockIdx.x * 128;
    const int wm = (wid & 3) * 32;       // warp m offset in tile
    const int wn = (wid >> 2) * 64;      // warp n offset in tile

    float acc[2][8][4];
#pragma unroll
    for (int i = 0; i < 2; i++)
#pragma unroll
        for (int j = 0; j < 8; j++)
#pragma unroll
            for (int c = 0; c < 4; c++) acc[i][j][c] = 0.f;

    const int ns = K / 32;

    // ---- stage loader: 4 matrices x 128 rows x 4 x 16B chunks via cp.async ----
    auto load_stage = [&](int buf, int kbase) {
        const uint32_t sb0 = sbase + buf * STG;
#pragma unroll
        for (int it = 0; it < 2; it++) {
            int idx = tid + 256 * it;            // 0..511
            int row = idx >> 2, c = idx & 3;
            uint32_t soff = (uint32_t)((row * ROWP + c * 8) * 2);
            const size_t ao = (size_t)(bm + row) * K + kbase + c * 8;
            cpa16(sb0 + OFF_AH + soff, Ah + ao);
            cpa16(sb0 + OFF_AL + soff, Al + ao);
            int br = bn + row; if (br >= N) br = 0;
            const size_t bo = (size_t)br * K + kbase + c * 8;
            cpa16(sb0 + OFF_BH + soff, Bh + bo);
            cpa16(sb0 + OFF_BL + soff, Bl + bo);
        }
    };

    load_stage(0, 0);
    CP_COMMIT();
    if (ns > 1) load_stage(1, 32);
    CP_COMMIT();

    // ldmatrix lane->address components
    const int arow  = lane & 15;             // A: row within 16
    const int acol8 = (lane >> 4) * 8;       // A: k half
    const int brow  = (lane & 7) + ((lane >> 4) & 1) * 8;   // B: n within 16
    const int bcol8 = ((lane >> 3) & 1) * 8;                // B: k half

    for (int s = 0; s < ns; s++) {
        CP_WAIT1();
        __syncthreads();
        const uint32_t sb0 = sbase + (s & 1) * STG;
        const uint32_t sah = sb0 + OFF_AH, sal = sb0 + OFF_AL;
        const uint32_t sbh = sb0 + OFF_BH, sbl = sb0 + OFF_BL;

#pragma unroll
        for (int ks = 0; ks < 32; ks += 16) {
            uint32_t ah[2][4], al[2][4];
#pragma unroll
            for (int mt = 0; mt < 2; mt++) {
                uint32_t aoff = (uint32_t)(((wm + mt * 16 + arow) * ROWP + ks + acol8) * 2);
                ldsm_x4(ah[mt], sah + aoff);
                ldsm_x4(al[mt], sal + aoff);
            }
#pragma unroll
            for (int ng = 0; ng < 4; ng++) {
                uint32_t bh[4], bl[4];
                uint32_t boff = (uint32_t)(((wn + ng * 16 + brow) * ROWP + ks + bcol8) * 2);
                ldsm_x4(bh, sbh + boff);
                ldsm_x4(bl, sbl + boff);
#pragma unroll
                for (int mt = 0; mt < 2; mt++) {
                    float* c0 = acc[mt][ng * 2 + 0];
                    float* c1 = acc[mt][ng * 2 + 1];
                    mma_bf16(c0, ah[mt], bh + 0);
                    mma_bf16(c0, ah[mt], bl + 0);
                    mma_bf16(c0, al[mt], bh + 0);
                    mma_bf16(c1, ah[mt], bh + 2);
                    mma_bf16(c1, ah[mt], bl + 2);
                    mma_bf16(c1, al[mt], bh + 2);
                }
            }
        }
        __syncthreads();
        if (s + 2 < ns) {
            load_stage(s & 1, (s + 2) * 32);
        }
        CP_COMMIT();
    }

    // ---- epilogue ----
#pragma unroll
    for (int mt = 0; mt < 2; mt++) {
        int r0 = bm + wm + mt * 16 + (lane >> 2);
        int r1 = r0 + 8;
#pragma unroll
        for (int nt = 0; nt < 8; nt++) {
            int col = bn + wn + nt * 8 + (lane & 3) * 2;
            if (col < N) {
                float* a = acc[mt][nt];
                *(float2*)(C + (size_t)r0 * N + col) = make_float2(a[0], a[1]);
                *(float2*)(C + (size_t)r1 * N + col) = make_float2(a[2], a[3]);
            }
        }
    }
}

// ============ conv(q,k) + silu + l2norm, and beta/g scalars ============
__global__ __launch_bounds__(512)
void conv_qk_kernel(const float* __restrict__ proj, const float* __restrict__ conv_w,
                    const float* __restrict__ A_log, const float* __restrict__ dt_bias,
                    float* __restrict__ qo, float* __restrict__ ko,
                    float* __restrict__ beta_o, float* __restrict__ g_o_)
{
    const int bt = blockIdx.x;
    const int t  = bt & (TT - 1);
    const int warp = threadIdx.x >> 5, lane = threadIdx.x & 31;

    float r[2];
#pragma unroll
    for (int s = 0; s < 2; s++) {
        int ch = warp * 64 + s * 32 + lane;
        float acc = 0.f;
#pragma unroll
        for (int kk = 0; kk < KSZ; kk++) {
            int tt = t - 3 + kk;
            float xv = (tt >= 0) ? proj[(size_t)(bt - 3 + kk) * IPD + ch] : 0.f;
            acc = fmaf(xv, conv_w[ch * KSZ + kk], acc);
        }
        r[s] = silu_f(acc);
    }
    float ss = r[0]*r[0] + r[1]*r[1];
#pragma unroll
    for (int o = 16; o; o >>= 1) ss += __shfl_xor_sync(0xffffffffu, ss, o);
    float inv = 1.f / fmaxf(sqrtf(ss), 1e-12f);

    if (warp < 8) {
        float* dst = qo + ((size_t)bt * NKH + warp) * DK;
        dst[lane] = r[0] * inv; dst[lane + 32] = r[1] * inv;
    } else {
        float* dst = ko + ((size_t)bt * NKH + (warp - 8)) * DK;
        dst[lane] = r[0] * inv; dst[lane + 32] = r[1] * inv;
    }

    if (threadIdx.x < NVH) {
        int h = threadIdx.x;
        float braw = proj[(size_t)bt * IPD + CD + VD + h];
        float araw = proj[(size_t)bt * IPD + CD + VD + NVH + h];
        beta_o[bt * NVH + h] = 1.f / (1.f + expf(-braw));
        float si = araw + dt_bias[h];
        float sp = (si > 20.f) ? si : log1pf(expf(si));
        g_o_[bt * NVH + h] = -expf(A_log[h]) * sp;
    }
}

// ============ conv(v) + silu ============
__global__ __launch_bounds__(256)
void conv_v_kernel(const float* __restrict__ proj, const float* __restrict__ conv_w,
                   float* __restrict__ vo)
{
    int idx = blockIdx.x * blockDim.x + threadIdx.x;
    int cv = idx & (VD - 1);
    int bt = idx >> 11;
    int t  = bt & (TT - 1);
    int ch = 2 * KD + cv;
    float acc = 0.f;
#pragma unroll
    for (int kk = 0; kk < KSZ; kk++) {
        int tt = t - 3 + kk;
        float xv = (tt >= 0) ? proj[(size_t)(bt - 3 + kk) * IPD + ch] : 0.f;
        acc = fmaf(xv, conv_w[ch * KSZ + kk], acc);
    }
    vo[idx] = silu_f(acc);
}

// ============ delta-rule recurrence (v3: depth-3 pipeline) ============
#define RCOLS 32
#define RST   3

__global__ __launch_bounds__(64)
void recur_kernel(const float* __restrict__ qarr, const float* __restrict__ karr,
                  const float* __restrict__ varr, const float* __restrict__ garr,
                  const float* __restrict__ barr, float* __restrict__ oarr)
{
    const int cta = blockIdx.x;
    const int cg  = cta & 3;
    const int h   = (cta >> 2) & 15;
    const int b   = cta >> 6;
    const int kh  = h >> 1;
    const int j    = threadIdx.x;
    const int col  = (j >> 1);
    const int half = j & 1;

    __shared__ __align__(16) float ks[RST][DK + 2];
    __shared__ __align__(16) float qs[RST][DK + 2];
    __shared__ float vs[RST][RCOLS];
    __shared__ float sc[RST][2];

    unsigned long long S2[16];
#pragma unroll
    for (int i = 0; i < 16; i++) S2[i] = 0ull;

    const size_t btb = (size_t)b * TT;
    const float* kbase = karr + (btb * NKH + kh) * DK;
    const float* qbase = qarr + (btb * NKH + kh) * DK;
    const float* vbase = varr + btb * VD + h * DV + cg * RCOLS;
    const float* gbase = garr + btb * NVH + h;
    const float* bbase = barr + btb * NVH + h;
    float*       obase = oarr + btb * VD + h * DV + cg * RCOLS + col;

    const int wj = (j < 32) ? j : (j + 2);

#pragma unroll
    for (int s = 0; s < 2; s++) {
        ks[s][wj] = kbase[(size_t)s * KD + j];
        qs[s][wj] = qbase[(size_t)s * KD + j];
        if (j < RCOLS) vs[s][j] = vbase[(size_t)s * VD + j];
        if (j == 0) sc[s][0] = expf(gbase[(size_t)s * NVH]);
        if (j == 1) sc[s][1] = bbase[(size_t)s * NVH];
    }
    float Ak = kbase[(size_t)2 * KD + j];
    float Aq = qbase[(size_t)2 * KD + j];
    float Av = (j < RCOLS) ? vbase[(size_t)2 * VD + j] : 0.f;
    float Ag = (j == 0) ? gbase[(size_t)2 * NVH] : 0.f;
    float Ab = (j == 1) ? bbase[(size_t)2 * NVH] : 0.f;
    __syncthreads();

    int p = 0;
    for (int t = 0; t < TT; t++) {
        float Bk = 0.f, Bq = 0.f, Bv = 0.f, Bg = 0.f, Bb2v = 0.f;
        if (t + 3 < TT) {
            const size_t o3 = (size_t)(t + 3);
            Bk = kbase[o3 * KD + j];
            Bq = qbase[o3 * KD + j];
            if (j < RCOLS) Bv = vbase[o3 * VD + j];
            if (j == 0) Bg = gbase[o3 * NVH];
            if (j == 1) Bb2v = bbase[o3 * NVH];
        }

        const float eg   = sc[p][0];
        const float beta = sc[p][1];
        const unsigned long long eg2 = pack2(eg, eg);
        const unsigned long long* k2 = (const unsigned long long*)ks[p] + half * 17;
        const unsigned long long* q2 = (const unsigned long long*)qs[p] + half * 17;

        unsigned long long dk2[4] = {0ull,0ull,0ull,0ull};
#pragma unroll
        for (int i = 0; i < 16; i++) {
            fmul2(S2[i], S2[i], eg2);
            ffma2(dk2[i & 3], S2[i], k2[i]);
        }
        fadd2(dk2[0], dk2[0], dk2[1]);
        fadd2(dk2[2], dk2[2], dk2[3]);
        fadd2(dk2[0], dk2[0], dk2[2]);
        float dkh = lo2(dk2[0]) + hi2(dk2[0]);
        dkh += __shfl_xor_sync(0xffffffffu, dkh, 1);

        float delta = beta * (vs[p][col] - dkh);
        const unsigned long long d2 = pack2(delta, delta);

        unsigned long long o2[4] = {0ull,0ull,0ull,0ull};
#pragma unroll
        for (int i = 0; i < 16; i++) {
            ffma2(S2[i], k2[i], d2);
            ffma2(o2[i & 3], S2[i], q2[i]);
        }
        fadd2(o2[0], o2[0], o2[1]);
        fadd2(o2[2], o2[2], o2[3]);
        fadd2(o2[0], o2[0], o2[2]);
        float oh = lo2(o2[0]) + hi2(o2[0]);
        oh += __shfl_xor_sync(0xffffffffu, oh, 1);
        if (half == 0) obase[(size_t)t * VD] = oh * SCALE;

        if (t + 2 < TT) {
            int pn = p + 2; if (pn >= RST) pn -= RST;
            ks[pn][wj] = Ak;
            qs[pn][wj] = Aq;
            if (j < RCOLS) vs[pn][j] = Av;
            if (j == 0) sc[pn][0] = expf(Ag);
            if (j == 1) sc[pn][1] = Ab;
        }
        Ak = Bk; Aq = Bq; Av = Bv; Ag = Bg; Ab = Bb2v;

        __syncthreads();
        if (++p == RST) p = 0;
    }
}

// ============ RMSNorm * silu(z) gate -> bf16 hi/lo ============
__global__ __launch_bounds__(256)
void gate_kernel(const float* __restrict__ o, const float* __restrict__ proj,
                 const float* __restrict__ nw,
                 __nv_bfloat16* __restrict__ gh, __nv_bfloat16* __restrict__ gl)
{
    int gw = (blockIdx.x * blockDim.x + threadIdx.x) >> 5;
    int lane = threadIdx.x & 31;
    int h  = gw & 15;
    int bt = gw >> 4;

    const float* orow = o + (size_t)bt * VD + h * DV;
    float v[4]; float ss = 0.f;
#pragma unroll
    for (int s = 0; s < 4; s++) { v[s] = orow[lane + 32 * s]; ss = fmaf(v[s], v[s], ss); }
#pragma unroll
    for (int m = 16; m; m >>= 1) ss += __shfl_xor_sync(0xffffffffu, ss, m);
    float rstd = rsqrtf(ss * (1.f / DV) + EPSR);

#pragma unroll
    for (int s = 0; s < 4; s++) {
        int dv = lane + 32 * s;
        float z = proj[(size_t)bt * IPD + CD + h * DV + dv];
        float gv = nw[dv] * v[s] * rstd * silu_f(z);
        __nv_bfloat16 hb = __float2bfloat16(gv);
        size_t idx = (size_t)bt * VD + h * DV + dv;
        gh[idx] = hb;
        gl[idx] = __float2bfloat16(gv - __bfloat162float(hb));
    }
}

// ---------------- launch ----------------
extern "C" void kernel_launch(void* const* d_in, const int* in_sizes, int n_in,
                              void* d_out, int out_size)
{
    const float* x          = (const float*)d_in[0];
    const float* in_proj_w  = (const float*)d_in[2];
    const float* conv_w     = (const float*)d_in[3];
    const float* dt_bias    = (const float*)d_in[4];
    const float* A_log      = (const float*)d_in[5];
    const float* norm_w     = (const float*)d_in[6];
    const float* out_proj_w = (const float*)d_in[7];
    float* out = (float*)d_out;

    float *proj, *q, *k, *v, *beta, *gdec, *o;
    __nv_bfloat16 *xh, *xl, *wih, *wil, *woh, *wol, *gh, *gl;
    cudaGetSymbolAddress((void**)&proj, g_proj);
    cudaGetSymbolAddress((void**)&q,    g_q);
    cudaGetSymbolAddress((void**)&k,    g_k);
    cudaGetSymbolAddress((void**)&v,    g_v);
    cudaGetSymbolAddress((void**)&beta, g_beta);
    cudaGetSymbolAddress((void**)&gdec, g_gdec);
    cudaGetSymbolAddress((void**)&o,    g_o);
    cudaGetSymbolAddress((void**)&xh,  g_xh);
    cudaGetSymbolAddress((void**)&xl,  g_xl);
    cudaGetSymbolAddress((void**)&wih, g_wih);
    cudaGetSymbolAddress((void**)&wil, g_wil);
    cudaGetSymbolAddress((void**)&woh, g_woh);
    cudaGetSymbolAddress((void**)&wol, g_wol);
    cudaGetSymbolAddress((void**)&gh,  g_gh);
    cudaGetSymbolAddress((void**)&gl,  g_gl);

    cudaFuncSetAttribute(gemm_bf16split_kernel, cudaFuncAttributeMaxDynamicSharedMemorySize, GSMEM);

    // 0) fp32 -> bf16 hi/lo splits
    {
        int n1 = BT * HID;
        split_kernel<<<(n1 + 255) / 256, 256>>>(x, xh, xl, n1);
        int n2 = IPD * HID;
        split_kernel<<<(n2 + 255) / 256, 256>>>(in_proj_w, wih, wil, n2);
        int n3 = HID * VD;
        split_kernel<<<(n3 + 255) / 256, 256>>>(out_proj_w, woh, wol, n3);
    }

    // 1) in_proj on tensor cores: proj[BT, IPD] = x @ W^T
    gemm_bf16split_kernel<<<dim3((IPD + 127) / 128, BT / 128), 256, GSMEM>>>(
        xh, xl, wih, wil, proj, BT, IPD, HID);

    // 2) conv + activations
    conv_qk_kernel<<<BT, 512>>>(proj, conv_w, A_log, dt_bias, q, k, beta, gdec);
    conv_v_kernel<<<(BT * VD) / 256, 256>>>(proj, conv_w, v);

    // 3) recurrence
    recur_kernel<<<BB * NVH * 4, 64>>>(q, k, v, gdec, beta, o);

    // 4) norm/gate (emits bf16 hi/lo) + out_proj on tensor cores
    gate_kernel<<<(BT * NVH) / 8, 256>>>(o, proj, norm_w, gh, gl);
    gemm_bf16split_kernel<<<dim3(HID / 128, BT / 128), 256, GSMEM>>>(
        gh, gl, woh, wol, out, BT, HID, VD);
}

// round 8
// speedup vs baseline: 1.9562x; 1.0865x over previous
#include <cuda_runtime.h>
#include <cuda_bf16.h>
#include <math.h>
#include <stdint.h>

// ---------------- problem constants ----------------
#define BB   2
#define TT   1024
#define HID  2048
#define NKH  8
#define NVH  16
#define DK   64
#define DV   128
#define KSZ  4
#define KD   (NKH*DK)          // 512
#define VD   (NVH*DV)          // 2048
#define CD   (2*KD + VD)       // 3072
#define IPD  (CD + VD + 2*NVH) // 5152
#define BT   (BB*TT)           // 2048
#define EPSR 1e-6f
#define SCALE 0.125f           // DK^-0.5

// ---------------- scratch (__device__ globals; no allocs allowed) ----------------
__device__ float g_proj [(size_t)BT * IPD];
__device__ float g_q    [(size_t)BT * KD];
__device__ float g_k    [(size_t)BT * KD];
__device__ float g_v    [(size_t)BT * VD];
__device__ float g_beta [(size_t)BT * NVH];
__device__ float g_gdec [(size_t)BT * NVH];
__device__ float g_o    [(size_t)BT * VD];

// bf16 hi/lo split operands for tensor-core GEMMs
__device__ __nv_bfloat16 g_xh [(size_t)BT * HID];
__device__ __nv_bfloat16 g_xl [(size_t)BT * HID];
__device__ __nv_bfloat16 g_wih[(size_t)IPD * HID];
__device__ __nv_bfloat16 g_wil[(size_t)IPD * HID];
__device__ __nv_bfloat16 g_woh[(size_t)HID * VD];
__device__ __nv_bfloat16 g_wol[(size_t)HID * VD];
__device__ __nv_bfloat16 g_gh [(size_t)BT * VD];
__device__ __nv_bfloat16 g_gl [(size_t)BT * VD];

// ---------------- f32x2 packed helpers ----------------
__device__ __forceinline__ unsigned long long pack2(float lo, float hi) {
    unsigned long long r;
    asm("mov.b64 %0, {%1, %2};" : "=l"(r) : "f"(lo), "f"(hi));
    return r;
}
__device__ __forceinline__ void ffma2(unsigned long long &d, unsigned long long a, unsigned long long b) {
    asm("fma.rn.f32x2 %0, %1, %2, %0;" : "+l"(d) : "l"(a), "l"(b));
}
__device__ __forceinline__ void fmul2(unsigned long long &d, unsigned long long a, unsigned long long b) {
    asm("mul.rn.f32x2 %0, %1, %2;" : "=l"(d) : "l"(a), "l"(b));
}
__device__ __forceinline__ void fadd2(unsigned long long &d, unsigned long long a, unsigned long long b) {
    asm("add.rn.f32x2 %0, %1, %2;" : "=l"(d) : "l"(a), "l"(b));
}
__device__ __forceinline__ float lo2(unsigned long long v) { return __uint_as_float((unsigned)(v & 0xffffffffull)); }
__device__ __forceinline__ float hi2(unsigned long long v) { return __uint_as_float((unsigned)(v >> 32)); }

__device__ __forceinline__ float silu_f(float x) { return x / (1.f + expf(-x)); }

// ---------------- HMMA / ldmatrix / cp.async helpers (sm_80+ ISA) ----------------
__device__ __forceinline__ uint32_t smem_u32(const void* p) {
    uint32_t a;
    asm("{ .reg .u64 t; cvta.to.shared.u64 t, %1; cvt.u32.u64 %0, t; }" : "=r"(a) : "l"(p));
    return a;
}
__device__ __forceinline__ void ldsm_x4(uint32_t* r, uint32_t addr) {
    asm volatile("ldmatrix.sync.aligned.m8n8.x4.shared.b16 {%0,%1,%2,%3}, [%4];"
        : "=r"(r[0]), "=r"(r[1]), "=r"(r[2]), "=r"(r[3]) : "r"(addr));
}
__device__ __forceinline__ void mma_bf16(float* c, const uint32_t* a, const uint32_t* b) {
    asm volatile(
        "mma.sync.aligned.m16n8k16.row.col.f32.bf16.bf16.f32 "
        "{%0,%1,%2,%3}, {%4,%5,%6,%7}, {%8,%9}, {%0,%1,%2,%3};"
        : "+f"(c[0]), "+f"(c[1]), "+f"(c[2]), "+f"(c[3])
        : "r"(a[0]), "r"(a[1]), "r"(a[2]), "r"(a[3]), "r"(b[0]), "r"(b[1]));
}
__device__ __forceinline__ void cpa16(uint32_t dst, const void* src) {
    asm volatile("cp.async.cg.shared.global [%0], [%1], 16;" :: "r"(dst), "l"(src));
}
#define CP_COMMIT() asm volatile("cp.async.commit_group;" ::: "memory")
#define CP_WAIT1()  asm volatile("cp.async.wait_group 1;" ::: "memory")

// ============ fp32 -> bf16 hi/lo split ============
__global__ __launch_bounds__(256)
void split_kernel(const float* __restrict__ in, __nv_bfloat16* __restrict__ hi,
                  __nv_bfloat16* __restrict__ lo, int n)
{
    int i = blockIdx.x * blockDim.x + threadIdx.x;
    if (i < n) {
        float x = in[i];
        __nv_bfloat16 h = __float2bfloat16(x);
        float r = x - __bfloat162float(h);
        hi[i] = h;
        lo[i] = __float2bfloat16(r);
    }
}

// ============ tensor-core GEMM: C[M,N] = A[M,K] @ B[N,K]^T (bf16 hi/lo split) ============
// tile 128x128x32, 256 threads (8 warps, warp = 32m x 64n), cp.async double buffer.
#define ROWP   40                        // smem row pitch in bf16 elems (80B, ldmatrix conflict-free)
#define ARR    (128 * ROWP * 2)          // 10240 B per matrix tile
#define OFF_AH 0
#define OFF_AL ARR
#define OFF_BH (2*ARR)
#define OFF_BL (3*ARR)
#define STG    (4*ARR)                   // 40960 B per stage
#define GSMEM  (2*STG)                   // 81920 B

__global__ __launch_bounds__(256, 2)
void gemm_bf16split_kernel(const __nv_bfloat16* __restrict__ Ah, const __nv_bfloat16* __restrict__ Al,
                           const __nv_bfloat16* __restrict__ Bh, const __nv_bfloat16* __restrict__ Bl,
                           float* __restrict__ C, int M, int N, int K)
{
    extern __shared__ __align__(128) char smem[];
    const uint32_t sbase = smem_u32(smem);
    const int tid  = threadIdx.x;
    const int wid  = tid >> 5, lane = tid & 31;
    const int bm = blockIdx.y * 128;
    const int bn = blockIdx.x * 128;
    const int wm = (wid & 3) * 32;       // warp m offset in tile
    const int wn = (wid >> 2) * 64;      // warp n offset in tile

    float acc[2][8][4];
#pragma unroll
    for (int i = 0; i < 2; i++)
#pragma unroll
        for (int j = 0; j < 8; j++)
#pragma unroll
            for (int c = 0; c < 4; c++) acc[i][j][c] = 0.f;

    const int ns = K / 32;

    // ---- stage loader: 4 matrices x 128 rows x 4 x 16B chunks via cp.async ----
    auto load_stage = [&](int buf, int kbase) {
        const uint32_t sb0 = sbase + buf * STG;
#pragma unroll
        for (int it = 0; it < 2; it++) {
            int idx = tid + 256 * it;            // 0..511
            int row = idx >> 2, c = idx & 3;
            uint32_t soff = (uint32_t)((row * ROWP + c * 8) * 2);
            const size_t ao = (size_t)(bm + row) * K + kbase + c * 8;
            cpa16(sb0 + OFF_AH + soff, Ah + ao);
            cpa16(sb0 + OFF_AL + soff, Al + ao);
            int br = bn + row; if (br >= N) br = 0;
            const size_t bo = (size_t)br * K + kbase + c * 8;
            cpa16(sb0 + OFF_BH + soff, Bh + bo);
            cpa16(sb0 + OFF_BL + soff, Bl + bo);
        }
    };

    load_stage(0, 0);
    CP_COMMIT();
    if (ns > 1) load_stage(1, 32);
    CP_COMMIT();

    // ldmatrix lane->address components
    const int arow  = lane & 15;             // A: row within 16
    const int acol8 = (lane >> 4) * 8;       // A: k half
    const int brow  = (lane & 7) + ((lane >> 4) & 1) * 8;   // B: n within 16
    const int bcol8 = ((lane >> 3) & 1) * 8;                // B: k half

    for (int s = 0; s < ns; s++) {
        CP_WAIT1();
        __syncthreads();
        const uint32_t sb0 = sbase + (s & 1) * STG;
        const uint32_t sah = sb0 + OFF_AH, sal = sb0 + OFF_AL;
        const uint32_t sbh = sb0 + OFF_BH, sbl = sb0 + OFF_BL;

#pragma unroll
        for (int ks = 0; ks < 32; ks += 16) {
            uint32_t ah[2][4], al[2][4];
#pragma unroll
            for (int mt = 0; mt < 2; mt++) {
                uint32_t aoff = (uint32_t)(((wm + mt * 16 + arow) * ROWP + ks + acol8) * 2);
                ldsm_x4(ah[mt], sah + aoff);
                ldsm_x4(al[mt], sal + aoff);
            }
#pragma unroll
            for (int ng = 0; ng < 4; ng++) {
                uint32_t bh[4], bl[4];
                uint32_t boff = (uint32_t)(((wn + ng * 16 + brow) * ROWP + ks + bcol8) * 2);
                ldsm_x4(bh, sbh + boff);
                ldsm_x4(bl, sbl + boff);
#pragma unroll
                for (int mt = 0; mt < 2; mt++) {
                    float* c0 = acc[mt][ng * 2 + 0];
                    float* c1 = acc[mt][ng * 2 + 1];
                    mma_bf16(c0, ah[mt], bh + 0);
                    mma_bf16(c0, ah[mt], bl + 0);
                    mma_bf16(c0, al[mt], bh + 0);
                    mma_bf16(c1, ah[mt], bh + 2);
                    mma_bf16(c1, ah[mt], bl + 2);
                    mma_bf16(c1, al[mt], bh + 2);
                }
            }
        }
        __syncthreads();
        if (s + 2 < ns) {
            load_stage(s & 1, (s + 2) * 32);
        }
        CP_COMMIT();
    }

    // ---- epilogue ----
#pragma unroll
    for (int mt = 0; mt < 2; mt++) {
        int r0 = bm + wm + mt * 16 + (lane >> 2);
        int r1 = r0 + 8;
#pragma unroll
        for (int nt = 0; nt < 8; nt++) {
            int col = bn + wn + nt * 8 + (lane & 3) * 2;
            if (col < N) {
                float* a = acc[mt][nt];
                *(float2*)(C + (size_t)r0 * N + col) = make_float2(a[0], a[1]);
                *(float2*)(C + (size_t)r1 * N + col) = make_float2(a[2], a[3]);
            }
        }
    }
}

// ============ conv(q,k) + silu + l2norm, and beta/g scalars ============
__global__ __launch_bounds__(512)
void conv_qk_kernel(const float* __restrict__ proj, const float* __restrict__ conv_w,
                    const float* __restrict__ A_log, const float* __restrict__ dt_bias,
                    float* __restrict__ qo, float* __restrict__ ko,
                    float* __restrict__ beta_o, float* __restrict__ g_o_)
{
    const int bt = blockIdx.x;
    const int t  = bt & (TT - 1);
    const int warp = threadIdx.x >> 5, lane = threadIdx.x & 31;

    float r[2];
#pragma unroll
    for (int s = 0; s < 2; s++) {
        int ch = warp * 64 + s * 32 + lane;
        float acc = 0.f;
#pragma unroll
        for (int kk = 0; kk < KSZ; kk++) {
            int tt = t - 3 + kk;
            float xv = (tt >= 0) ? proj[(size_t)(bt - 3 + kk) * IPD + ch] : 0.f;
            acc = fmaf(xv, conv_w[ch * KSZ + kk], acc);
        }
        r[s] = silu_f(acc);
    }
    float ss = r[0]*r[0] + r[1]*r[1];
#pragma unroll
    for (int o = 16; o; o >>= 1) ss += __shfl_xor_sync(0xffffffffu, ss, o);
    float inv = 1.f / fmaxf(sqrtf(ss), 1e-12f);

    if (warp < 8) {
        float* dst = qo + ((size_t)bt * NKH + warp) * DK;
        dst[lane] = r[0] * inv; dst[lane + 32] = r[1] * inv;
    } else {
        float* dst = ko + ((size_t)bt * NKH + (warp - 8)) * DK;
        dst[lane] = r[0] * inv; dst[lane + 32] = r[1] * inv;
    }

    if (threadIdx.x < NVH) {
        int h = threadIdx.x;
        float braw = proj[(size_t)bt * IPD + CD + VD + h];
        float araw = proj[(size_t)bt * IPD + CD + VD + NVH + h];
        beta_o[bt * NVH + h] = 1.f / (1.f + expf(-braw));
        float si = araw + dt_bias[h];
        float sp = (si > 20.f) ? si : log1pf(expf(si));
        g_o_[bt * NVH + h] = -expf(A_log[h]) * sp;
    }
}

// ============ conv(v) + silu ============
__global__ __launch_bounds__(256)
void conv_v_kernel(const float* __restrict__ proj, const float* __restrict__ conv_w,
                   float* __restrict__ vo)
{
    int idx = blockIdx.x * blockDim.x + threadIdx.x;
    int cv = idx & (VD - 1);
    int bt = idx >> 11;
    int t  = bt & (TT - 1);
    int ch = 2 * KD + cv;
    float acc = 0.f;
#pragma unroll
    for (int kk = 0; kk < KSZ; kk++) {
        int tt = t - 3 + kk;
        float xv = (tt >= 0) ? proj[(size_t)(bt - 3 + kk) * IPD + ch] : 0.f;
        acc = fmaf(xv, conv_w[ch * KSZ + kk], acc);
    }
    vo[idx] = silu_f(acc);
}

// ============ delta-rule recurrence, v4: single-warp CTAs, 8-way col split ============
// grid = BB*NVH*8 = 256 CTAs; 32 threads (1 warp). Lane pair (2c,2c+1) owns column c
// of a 16-column group; half = lane&1 owns k-rows [half*32, half*32+32).
// No __syncthreads: warp-private smem staging with __syncwarp (cheap).
#define RCOLS 16
#define RST   3

__global__ __launch_bounds__(32)
void recur_kernel(const float* __restrict__ qarr, const float* __restrict__ karr,
                  const float* __restrict__ varr, const float* __restrict__ garr,
                  const float* __restrict__ barr, float* __restrict__ oarr)
{
    const int cta = blockIdx.x;
    const int cg  = cta & 7;              // 16-col group
    const int h   = (cta >> 3) & 15;
    const int b   = cta >> 7;
    const int kh  = h >> 1;
    const int j    = threadIdx.x;         // 0..31
    const int col  = (j >> 1);            // 0..15
    const int half = j & 1;

    __shared__ __align__(16) float ks[RST][DK + 2];
    __shared__ __align__(16) float qs[RST][DK + 2];
    __shared__ float vs[RST][RCOLS];
    __shared__ float sc[RST][2];          // [exp(g), beta]

    unsigned long long S2[16];
#pragma unroll
    for (int i = 0; i < 16; i++) S2[i] = 0ull;

    const size_t btb = (size_t)b * TT;
    const float* kbase = karr + (btb * NKH + kh) * DK;            // + t*512
    const float* qbase = qarr + (btb * NKH + kh) * DK;
    const float* vbase = varr + btb * VD + h * DV + cg * RCOLS;   // + t*2048
    const float* gbase = garr + btb * NVH + h;                    // + t*16
    const float* bbase = barr + btb * NVH + h;
    float*       obase = oarr + btb * VD + h * DV + cg * RCOLS + col;

    // ---- prologue: stage t=0, t=1 directly; issue loads for t=2 ----
#pragma unroll
    for (int s = 0; s < 2; s++) {
        ks[s][j]      = kbase[(size_t)s * KD + j];
        ks[s][j + 34] = kbase[(size_t)s * KD + j + 32];
        qs[s][j]      = qbase[(size_t)s * KD + j];
        qs[s][j + 34] = qbase[(size_t)s * KD + j + 32];
        if (j < RCOLS) vs[s][j] = vbase[(size_t)s * VD + j];
        if (j == 0) sc[s][0] = expf(gbase[(size_t)s * NVH]);
        if (j == 1) sc[s][1] = bbase[(size_t)s * NVH];
    }
    float Ak0 = kbase[(size_t)2 * KD + j];
    float Ak1 = kbase[(size_t)2 * KD + j + 32];
    float Aq0 = qbase[(size_t)2 * KD + j];
    float Aq1 = qbase[(size_t)2 * KD + j + 32];
    float Av  = (j < RCOLS) ? vbase[(size_t)2 * VD + j] : 0.f;
    float Ag  = (j == 0) ? gbase[(size_t)2 * NVH] : 0.f;
    float Ab  = (j == 1) ? bbase[(size_t)2 * NVH] : 0.f;
    __syncwarp();

    int p = 0;
    for (int t = 0; t < TT; t++) {
        // ---- issue loads for t+3 ----
        float Bk0 = 0.f, Bk1 = 0.f, Bq0 = 0.f, Bq1 = 0.f, Bv = 0.f, Bg = 0.f, Bb = 0.f;
        if (t + 3 < TT) {
            const size_t o3 = (size_t)(t + 3);
            Bk0 = kbase[o3 * KD + j];
            Bk1 = kbase[o3 * KD + j + 32];
            Bq0 = qbase[o3 * KD + j];
            Bq1 = qbase[o3 * KD + j + 32];
            if (j < RCOLS) Bv = vbase[o3 * VD + j];
            if (j == 0) Bg = gbase[o3 * NVH];
            if (j == 1) Bb = bbase[o3 * NVH];
        }

        // ---- compute on buffer p ----
        const float eg   = sc[p][0];
        const float beta = sc[p][1];
        const unsigned long long eg2 = pack2(eg, eg);
        const unsigned long long* k2 = (const unsigned long long*)ks[p] + half * 17;
        const unsigned long long* q2 = (const unsigned long long*)qs[p] + half * 17;

        unsigned long long dk2[4] = {0ull,0ull,0ull,0ull};
#pragma unroll
        for (int i = 0; i < 16; i++) {
            fmul2(S2[i], S2[i], eg2);
            ffma2(dk2[i & 3], S2[i], k2[i]);
        }
        fadd2(dk2[0], dk2[0], dk2[1]);
        fadd2(dk2[2], dk2[2], dk2[3]);
        fadd2(dk2[0], dk2[0], dk2[2]);
        float dkh = lo2(dk2[0]) + hi2(dk2[0]);
        dkh += __shfl_xor_sync(0xffffffffu, dkh, 1);

        float delta = beta * (vs[p][col] - dkh);
        const unsigned long long d2 = pack2(delta, delta);

        unsigned long long o2[4] = {0ull,0ull,0ull,0ull};
#pragma unroll
        for (int i = 0; i < 16; i++) {
            ffma2(S2[i], k2[i], d2);
            ffma2(o2[i & 3], S2[i], q2[i]);
        }
        fadd2(o2[0], o2[0], o2[1]);
        fadd2(o2[2], o2[2], o2[3]);
        fadd2(o2[0], o2[0], o2[2]);
        float oh = lo2(o2[0]) + hi2(o2[0]);
        oh += __shfl_xor_sync(0xffffffffu, oh, 1);
        if (half == 0) obase[(size_t)t * VD] = oh * SCALE;

        // ---- store regs holding t+2 into buffer (t+2)%3 ----
        if (t + 2 < TT) {
            int pn = p + 2; if (pn >= RST) pn -= RST;
            ks[pn][j]      = Ak0;
            ks[pn][j + 34] = Ak1;
            qs[pn][j]      = Aq0;
            qs[pn][j + 34] = Aq1;
            if (j < RCOLS) vs[pn][j] = Av;
            if (j == 0) sc[pn][0] = expf(Ag);
            if (j == 1) sc[pn][1] = Ab;
        }
        Ak0 = Bk0; Ak1 = Bk1; Aq0 = Bq0; Aq1 = Bq1; Av = Bv; Ag = Bg; Ab = Bb;

        __syncwarp();
        if (++p == RST) p = 0;
    }
}

// ============ RMSNorm * silu(z) gate -> bf16 hi/lo ============
__global__ __launch_bounds__(256)
void gate_kernel(const float* __restrict__ o, const float* __restrict__ proj,
                 const float* __restrict__ nw,
                 __nv_bfloat16* __restrict__ gh, __nv_bfloat16* __restrict__ gl)
{
    int gw = (blockIdx.x * blockDim.x + threadIdx.x) >> 5;
    int lane = threadIdx.x & 31;
    int h  = gw & 15;
    int bt = gw >> 4;

    const float* orow = o + (size_t)bt * VD + h * DV;
    float v[4]; float ss = 0.f;
#pragma unroll
    for (int s = 0; s < 4; s++) { v[s] = orow[lane + 32 * s]; ss = fmaf(v[s], v[s], ss); }
#pragma unroll
    for (int m = 16; m; m >>= 1) ss += __shfl_xor_sync(0xffffffffu, ss, m);
    float rstd = rsqrtf(ss * (1.f / DV) + EPSR);

#pragma unroll
    for (int s = 0; s < 4; s++) {
        int dv = lane + 32 * s;
        float z = proj[(size_t)bt * IPD + CD + h * DV + dv];
        float gv = nw[dv] * v[s] * rstd * silu_f(z);
        __nv_bfloat16 hb = __float2bfloat16(gv);
        size_t idx = (size_t)bt * VD + h * DV + dv;
        gh[idx] = hb;
        gl[idx] = __float2bfloat16(gv - __bfloat162float(hb));
    }
}

// ---------------- launch ----------------
extern "C" void kernel_launch(void* const* d_in, const int* in_sizes, int n_in,
                              void* d_out, int out_size)
{
    const float* x          = (const float*)d_in[0];
    const float* in_proj_w  = (const float*)d_in[2];
    const float* conv_w     = (const float*)d_in[3];
    const float* dt_bias    = (const float*)d_in[4];
    const float* A_log      = (const float*)d_in[5];
    const float* norm_w     = (const float*)d_in[6];
    const float* out_proj_w = (const float*)d_in[7];
    float* out = (float*)d_out;

    float *proj, *q, *k, *v, *beta, *gdec, *o;
    __nv_bfloat16 *xh, *xl, *wih, *wil, *woh, *wol, *gh, *gl;
    cudaGetSymbolAddress((void**)&proj, g_proj);
    cudaGetSymbolAddress((void**)&q,    g_q);
    cudaGetSymbolAddress((void**)&k,    g_k);
    cudaGetSymbolAddress((void**)&v,    g_v);
    cudaGetSymbolAddress((void**)&beta, g_beta);
    cudaGetSymbolAddress((void**)&gdec, g_gdec);
    cudaGetSymbolAddress((void**)&o,    g_o);
    cudaGetSymbolAddress((void**)&xh,  g_xh);
    cudaGetSymbolAddress((void**)&xl,  g_xl);
    cudaGetSymbolAddress((void**)&wih, g_wih);
    cudaGetSymbolAddress((void**)&wil, g_wil);
    cudaGetSymbolAddress((void**)&woh, g_woh);
    cudaGetSymbolAddress((void**)&wol, g_wol);
    cudaGetSymbolAddress((void**)&gh,  g_gh);
    cudaGetSymbolAddress((void**)&gl,  g_gl);

    cudaFuncSetAttribute(gemm_bf16split_kernel, cudaFuncAttributeMaxDynamicSharedMemorySize, GSMEM);

    // 0) fp32 -> bf16 hi/lo splits
    {
        int n1 = BT * HID;
        split_kernel<<<(n1 + 255) / 256, 256>>>(x, xh, xl, n1);
        int n2 = IPD * HID;
        split_kernel<<<(n2 + 255) / 256, 256>>>(in_proj_w, wih, wil, n2);
        int n3 = HID * VD;
        split_kernel<<<(n3 + 255) / 256, 256>>>(out_proj_w, woh, wol, n3);
    }

    // 1) in_proj on tensor cores: proj[BT, IPD] = x @ W^T
    gemm_bf16split_kernel<<<dim3((IPD + 127) / 128, BT / 128), 256, GSMEM>>>(
        xh, xl, wih, wil, proj, BT, IPD, HID);

    // 2) conv + activations
    conv_qk_kernel<<<BT, 512>>>(proj, conv_w, A_log, dt_bias, q, k, beta, gdec);
    conv_v_kernel<<<(BT * VD) / 256, 256>>>(proj, conv_w, v);

    // 3) recurrence
    recur_kernel<<<BB * NVH * 8, 32>>>(q, k, v, gdec, beta, o);

    // 4) norm/gate (emits bf16 hi/lo) + out_proj on tensor cores
    gate_kernel<<<(BT * NVH) / 8, 256>>>(o, proj, norm_w, gh, gl);
    gemm_bf16split_kernel<<<dim3(HID / 128, BT / 128), 256, GSMEM>>>(
        gh, gl, woh, wol, out, BT, HID, VD);
}